// round 9
// baseline (speedup 1.0000x reference)
#include <cuda_runtime.h>
#include <cuda_fp16.h>
#include <math.h>
#include <stdint.h>

// ---------------- problem constants ----------------
#define Bz   16
#define T0   400
#define F0c  40
#define Hc   512
#define T1c  396
#define T3c  384
#define Kbot (Hc*Hc)   // 262144

// ---------------- scratch (device globals; no allocs allowed) ----------------
__device__ float g_x0[Bz*F0c*T0];
__device__ float g_bufA[Bz*Hc*T1c];
__device__ float g_bufB[Bz*Hc*T1c];
__device__ float g_x5[Bz*Hc*T3c];
__device__ float g_M[Bz*Kbot];
__device__ float g_sum[Hc];
__device__ float g_sumsq[Hc];
__device__ float g_scale[Hc];
__device__ float g_shift[Hc];
__device__ float g_scale4[Hc];
__device__ float g_shift4[Hc];
__device__ float g_scale5[Hc];
__device__ float g_shift5[Hc];
__device__ float g_h[Bz*Hc];
__device__ float g_hn[Bz*Hc];
__device__ float g_emb[Bz*Hc];
__device__ float g_zero[Hc];

// ---------------- helpers ----------------
__device__ __forceinline__ void f16_split2(float x0, float x1, uint32_t& hw, uint32_t& lw)
{
    __half2 h = __floats2half2_rn(x0, x1);
    float2 hf = __half22float2(h);
    __half2 l = __floats2half2_rn(x0 - hf.x, x1 - hf.y);
    hw = *(uint32_t*)&h;
    lw = *(uint32_t*)&l;
}

__device__ __forceinline__ void mma_f16_k16(float* d, const uint32_t* a, const uint32_t* b)
{
    asm volatile(
        "mma.sync.aligned.m16n8k16.row.col.f32.f16.f16.f32 "
        "{%0,%1,%2,%3}, {%4,%5,%6,%7}, {%8,%9}, {%0,%1,%2,%3};"
        : "+f"(d[0]), "+f"(d[1]), "+f"(d[2]), "+f"(d[3])
        : "r"(a[0]), "r"(a[1]), "r"(a[2]), "r"(a[3]), "r"(b[0]), "r"(b[1]));
}

__device__ __forceinline__ void ldsm_x4(uint32_t* r, uint32_t saddr)
{
    asm volatile("ldmatrix.sync.aligned.m8n8.x4.shared.b16 {%0,%1,%2,%3}, [%4];"
        : "=r"(r[0]), "=r"(r[1]), "=r"(r[2]), "=r"(r[3]) : "r"(saddr));
}

__device__ __forceinline__ void sts_v2(uint32_t saddr, uint32_t v0, uint32_t v1)
{
    asm volatile("st.shared.v2.u32 [%0], {%1,%2};" :: "r"(saddr), "r"(v0), "r"(v1));
}

__device__ __forceinline__ float relu20(float v)
{
    return fminf(fmaxf(v, 0.f), 20.f);
}

// ---------------- transpose [B,1,T,F] -> [B,F,T] ----------------
__global__ void transpose_kernel(const float* __restrict__ in, float* __restrict__ out)
{
    int idx = blockIdx.x * blockDim.x + threadIdx.x;
    if (idx >= Bz * T0 * F0c) return;
    int c = idx % F0c;
    int t = (idx / F0c) % T0;
    int b = idx / (F0c * T0);
    out[(b * F0c + c) * T0 + t] = in[idx];
}

// ---------------- FP16x3 tensor-core conv-as-GEMM (k16 + ldmatrix) ----------------
// Warp grid 4x2 (wm 0..3, wn 0..1), warp tile 32x32 (2 mt x 4 nt):
// block smem fragment reads/kstep = 2*128*64 + 4*64*64 = 32KB (was 40KB at 2x4),
// cutting the binding smem-BW per MAC by 22%.
// BM=128 BN=64 BK=16, 256 thr, double-buffered, row stride 12 words (LDSM conflict-free).
#define RSTR 12
template<int KW, int DIL, int MODE, bool STATS>
__global__ __launch_bounds__(256, 3)
void conv_gemm_f16k16(const float* __restrict__ A, const float* __restrict__ bias,
                      const float* __restrict__ X, float* __restrict__ Y,
                      const float* __restrict__ scA, const float* __restrict__ shA,
                      const float* __restrict__ scB, const float* __restrict__ shB,
                      int C, int Tin, int Tout, int CK, int Ntot,
                      int strideA, int strideX, int strideY)
{
    A += (size_t)blockIdx.z * strideA;
    X += (size_t)blockIdx.z * strideX;
    Y += (size_t)blockIdx.z * strideY;

    __shared__ uint32_t AsH[2][128][RSTR];
    __shared__ uint32_t AsL[2][128][RSTR];
    __shared__ uint32_t BsH[2][64][RSTR];
    __shared__ uint32_t BsL[2][64][RSTR];
    __shared__ float sScB[Hc];
    __shared__ float sShB[Hc];

    const int tid  = threadIdx.x;
    const int lane = tid & 31;
    const int warp = tid >> 5;
    const int wm = warp >> 1;      // 0..3 (32 rows each)
    const int wn = warp & 1;       // 0..1 (32 cols each)
    const int oBase = blockIdx.y * 128;
    const int nBase = blockIdx.x * 64;

    float acc[2][4][4];
    #pragma unroll
    for (int i = 0; i < 2; i++)
        #pragma unroll
        for (int j = 0; j < 4; j++)
            #pragma unroll
            for (int r = 0; r < 4; r++) acc[i][j][r] = 0.f;

    // A loader: row = tid>>1; even thr floats {0-3,8-11} -> words {0,1,4,5};
    // odd thr floats {4-7,12-15} -> words {2,3,6,7}
    const int aRow = tid >> 1;
    const int aC0  = (tid & 1) * 4;
    const int aW   = (tid & 1) * 2;
    // B loader: n = tid&63, floats bG*4..+3 -> words bG*2, bG*2+1
    const int bN  = tid & 63;
    const int bG  = tid >> 6;

    const int nIdx = nBase + bN;
    const bool nValid = (nIdx < Ntot);
    int nb = 0, nt0 = 0;
    if (nValid) { nb = nIdx / Tout; nt0 = nIdx - nb * Tout; }
    const float* Xbase = X + ((size_t)nb * C) * Tin + nt0;
    const float* Arow = A + (size_t)(oBase + aRow) * CK;

    const uint32_t baseAH = (uint32_t)__cvta_generic_to_shared(&AsH[0][0][0]);
    const uint32_t baseAL = (uint32_t)__cvta_generic_to_shared(&AsL[0][0][0]);
    const uint32_t baseBH = (uint32_t)__cvta_generic_to_shared(&BsH[0][0][0]);
    const uint32_t baseBL = (uint32_t)__cvta_generic_to_shared(&BsL[0][0][0]);
    const uint32_t bufA = 128 * RSTR * 4;
    const uint32_t bufB = 64 * RSTR * 4;

    const uint32_t stA = (aRow * RSTR + aW) * 4;
    const uint32_t stB = (bN * RSTR + bG * 2) * 4;

    // LDSM source offsets.
    // A (x4): lanes 0-7 rows r0-7 kLow | 8-15 rows r8-15 kLow | 16-23 r0-7 kHi | 24-31 r8-15 kHi
    const int aFragRow = (lane & 7) + ((lane >> 3) & 1) * 8;
    const int aFragWord = (lane >> 4) * 4;
    const uint32_t ldA0 = ((wm * 32 + aFragRow) * RSTR + aFragWord) * 4;  // + mt*16*RSTR*4
    // B (x4): covers 2 n8 tiles (16 rows) x k16:
    // m0 (n0-7,kL), m1 (n0-7,kH), m2 (n8-15,kL), m3 (n8-15,kH)
    const int bFragRow = (lane & 7) + ((lane >> 4) << 3);
    const int bFragWord = ((lane >> 3) & 1) * 4;
    const uint32_t ldB0 = ((wn * 32 + bFragRow) * RSTR + bFragWord) * 4;  // + p*16*RSTR*4

    // per-thread BN constants for MODE 2
    float aS = 1.f, aSh = 0.f, bS = 1.f, bSh = 0.f;
    if (MODE == 2) {
        aS  = scA[oBase + aRow];
        aSh = shA[oBase + aRow];
        bS  = scB[nIdx & (Hc - 1)];
        bSh = shB[nIdx & (Hc - 1)];
    }
    if (MODE == 1) {
        for (int i = tid; i < C; i += 256) {
            sScB[i] = scB[i];
            sShB[i] = shB[i];
        }
        __syncthreads();
    }

    float pa[8], pb[4];

    // ---- prefetch k0 = 0 ----
    {
        const float4 av = *(const float4*)(Arow + aC0);
        pa[0] = av.x; pa[1] = av.y; pa[2] = av.z; pa[3] = av.w;
        if (aC0 + 11 < CK) {
            const float4 av2 = *(const float4*)(Arow + aC0 + 8);
            pa[4] = av2.x; pa[5] = av2.y; pa[6] = av2.z; pa[7] = av2.w;
        } else {
            pa[4] = pa[5] = pa[6] = pa[7] = 0.f;
        }
        if (MODE == 2) {
            #pragma unroll
            for (int j = 0; j < 8; j++) pa[j] = relu20(aS * pa[j] + aSh);
        }
        #pragma unroll
        for (int p = 0; p < 4; p++) {
            int kkg = bG * 4 + p;
            float v = 0.f;
            if (nValid && kkg < CK) {
                int c = kkg / KW;
                int kw = kkg - c * KW;
                v = Xbase[c * Tin + kw * DIL];
                if (MODE == 1) v = relu20(sScB[c] * v + sShB[c]);
                if (MODE == 2) v = relu20(bS * v + bSh);
            }
            pb[p] = v;
        }
    }

    const int nSteps = (CK + 15) >> 4;
    int pbuf = 0;
    for (int s = 0; s < nSteps; s++) {
        // stage current k16 tile (fp16 hi/lo split), vectorized stores
        {
            const uint32_t offA = pbuf * bufA;
            const uint32_t offB = pbuf * bufB;
            uint32_t h0, l0, h1, l1;
            f16_split2(pa[0], pa[1], h0, l0);
            f16_split2(pa[2], pa[3], h1, l1);
            sts_v2(baseAH + offA + stA, h0, h1);
            sts_v2(baseAL + offA + stA, l0, l1);
            f16_split2(pa[4], pa[5], h0, l0);
            f16_split2(pa[6], pa[7], h1, l1);
            sts_v2(baseAH + offA + stA + 16, h0, h1);
            sts_v2(baseAL + offA + stA + 16, l0, l1);
            f16_split2(pb[0], pb[1], h0, l0);
            f16_split2(pb[2], pb[3], h1, l1);
            sts_v2(baseBH + offB + stB, h0, h1);
            sts_v2(baseBL + offB + stB, l0, l1);
        }
        __syncthreads();

        // prefetch next k16 tile
        if (s + 1 < nSteps) {
            int k0 = (s + 1) * 16;
            const float4 av = *(const float4*)(Arow + k0 + aC0);
            pa[0] = av.x; pa[1] = av.y; pa[2] = av.z; pa[3] = av.w;
            if (k0 + aC0 + 11 < CK) {
                const float4 av2 = *(const float4*)(Arow + k0 + aC0 + 8);
                pa[4] = av2.x; pa[5] = av2.y; pa[6] = av2.z; pa[7] = av2.w;
            } else {
                pa[4] = pa[5] = pa[6] = pa[7] = 0.f;
            }
            if (MODE == 2) {
                #pragma unroll
                for (int j = 0; j < 8; j++) pa[j] = relu20(aS * pa[j] + aSh);
            }
            #pragma unroll
            for (int p = 0; p < 4; p++) {
                int kkg = k0 + bG * 4 + p;
                float v = 0.f;
                if (nValid && kkg < CK) {
                    int c = kkg / KW;
                    int kw = kkg - c * KW;
                    v = Xbase[c * Tin + kw * DIL];
                    if (MODE == 1) v = relu20(sScB[c] * v + sShB[c]);
                    if (MODE == 2) v = relu20(bS * v + bSh);
                }
                pb[p] = v;
            }
        }

        // fragment loads via ldmatrix
        {
            const uint32_t offA = pbuf * bufA;
            const uint32_t offB = pbuf * bufB;
            uint32_t bHf[8], bLf[8];
            ldsm_x4(bHf,     baseBH + offB + ldB0);
            ldsm_x4(bHf + 4, baseBH + offB + ldB0 + 16 * RSTR * 4);
            ldsm_x4(bLf,     baseBL + offB + ldB0);
            ldsm_x4(bLf + 4, baseBL + offB + ldB0 + 16 * RSTR * 4);
            #pragma unroll
            for (int mt = 0; mt < 2; mt++) {
                const uint32_t mtOff = mt * 16 * RSTR * 4;
                uint32_t aHf[4], aLf[4];
                ldsm_x4(aHf, baseAH + offA + ldA0 + mtOff);
                ldsm_x4(aLf, baseAL + offA + ldA0 + mtOff);
                #pragma unroll
                for (int nt = 0; nt < 4; nt++) {
                    mma_f16_k16(acc[mt][nt], aHf, bLf + nt * 2);
                    mma_f16_k16(acc[mt][nt], aLf, bHf + nt * 2);
                    mma_f16_k16(acc[mt][nt], aHf, bHf + nt * 2);
                }
            }
        }

        pbuf ^= 1;
    }

    // epilogue
    #pragma unroll
    for (int mt = 0; mt < 2; mt++) {
        int row0 = oBase + wm * 32 + mt * 16 + (lane >> 2);
        float b0 = bias[row0];
        float b1 = bias[row0 + 8];
        float s0 = 0.f, q0 = 0.f, s1 = 0.f, q1 = 0.f;
        #pragma unroll
        for (int nt = 0; nt < 4; nt++) {
            int col0 = nBase + wn * 32 + nt * 8 + (lane & 3) * 2;
            #pragma unroll
            for (int cc = 0; cc < 2; cc++) {
                int col = col0 + cc;
                if (col < Ntot) {
                    float v0 = acc[mt][nt][cc]     + b0;
                    float v1 = acc[mt][nt][2 + cc] + b1;
                    int b = col / Tout;
                    int t = col - b * Tout;
                    size_t base = ((size_t)b * Hc) * Tout + t;
                    Y[base + (size_t)row0 * Tout]       = v0;
                    Y[base + (size_t)(row0 + 8) * Tout] = v1;
                    if (STATS) {
                        s0 += v0; q0 += v0 * v0;
                        s1 += v1; q1 += v1 * v1;
                    }
                }
            }
        }
        if (STATS) {
            #pragma unroll
            for (int off = 2; off >= 1; off >>= 1) {
                s0 += __shfl_down_sync(0xffffffffu, s0, off);
                q0 += __shfl_down_sync(0xffffffffu, q0, off);
                s1 += __shfl_down_sync(0xffffffffu, s1, off);
                q1 += __shfl_down_sync(0xffffffffu, q1, off);
            }
            if ((lane & 3) == 0) {
                atomicAdd(&g_sum[row0], s0);
                atomicAdd(&g_sumsq[row0], q0);
                atomicAdd(&g_sum[row0 + 8], s1);
                atomicAdd(&g_sumsq[row0 + 8], q1);
            }
        }
    }
}

// ---------------- BN finalize ----------------
__global__ void bn_finalize(const float* __restrict__ g, const float* __restrict__ be,
                            float* __restrict__ sc, float* __restrict__ sh, float invN)
{
    int c = threadIdx.x;   // 512
    float s = g_sum[c], q = g_sumsq[c];
    float m = s * invN;
    float var = q * invN - m * m;
    float a = g[c] * rsqrtf(var + 1e-5f);
    sc[c] = a;
    sh[c] = be[c] - a * m;
    g_sum[c] = 0.f;
    g_sumsq[c] = 0.f;
}

// ---------------- bottleneck ----------------
__global__ void zero_h()
{
    g_h[blockIdx.x * blockDim.x + threadIdx.x] = 0.f;
}

__global__ __launch_bounds__(512)
void bottleneck(const float* __restrict__ W)
{
    __shared__ float Ms[Bz][512];
    int warp = threadIdx.x >> 5, lane = threadIdx.x & 31;
    int o0 = blockIdx.x * 32 + warp * 2;
    int k0 = blockIdx.y * (Kbot / 32);

    float acc0[16], acc1[16];
    #pragma unroll
    for (int b = 0; b < 16; b++) { acc0[b] = 0.f; acc1[b] = 0.f; }

    for (int kt = 0; kt < Kbot / 32; kt += 512) {
        __syncthreads();
        #pragma unroll
        for (int i = 0; i < 16; i++) {
            int idx = threadIdx.x + i * 512;
            int b = idx >> 9, kk = idx & 511;
            Ms[b][kk] = g_M[b * Kbot + k0 + kt + kk];
        }
        __syncthreads();
        const float* w0p = W + (size_t)o0 * Kbot + k0 + kt;
        const float* w1p = w0p + Kbot;
        #pragma unroll
        for (int kk = lane * 4; kk < 512; kk += 128) {
            float4 w0 = *(const float4*)(w0p + kk);
            float4 w1 = *(const float4*)(w1p + kk);
            #pragma unroll
            for (int b = 0; b < 16; b++) {
                float4 m = *(const float4*)&Ms[b][kk];
                acc0[b] += w0.x * m.x + w0.y * m.y + w0.z * m.z + w0.w * m.w;
                acc1[b] += w1.x * m.x + w1.y * m.y + w1.z * m.z + w1.w * m.w;
            }
        }
    }
    #pragma unroll
    for (int b = 0; b < 16; b++) {
        float v0 = acc0[b], v1 = acc1[b];
        #pragma unroll
        for (int off = 16; off; off >>= 1) {
            v0 += __shfl_down_sync(0xffffffffu, v0, off);
            v1 += __shfl_down_sync(0xffffffffu, v1, off);
        }
        if (lane == 0) {
            atomicAdd(&g_h[b * Hc + o0], v0);
            atomicAdd(&g_h[b * Hc + o0 + 1], v1);
        }
    }
}

// ---------------- BN over batch + relu20 ----------------
__global__ void bn2d_relu(const float* __restrict__ bot_b, const float* __restrict__ gg,
                          const float* __restrict__ gb)
{
    int o = threadIdx.x;
    float v[16];
    float s = 0.f, sq = 0.f;
    #pragma unroll
    for (int b = 0; b < 16; b++) {
        float x = g_h[b * Hc + o] + bot_b[o];
        v[b] = x; s += x; sq += x * x;
    }
    float m = s * (1.f / 16.f);
    float var = sq * (1.f / 16.f) - m * m;
    float a = gg[o] * rsqrtf(var + 1e-5f);
    float d = gb[o] - a * m;
    #pragma unroll
    for (int b = 0; b < 16; b++) {
        float z = a * v[b] + d;
        g_hn[b * Hc + o] = fminf(fmaxf(z, 0.f), 20.f);
    }
}

// ---------------- embedding GEMV + bias ----------------
__global__ void emb_kernel(const float* __restrict__ h, const float* __restrict__ W,
                           const float* __restrict__ bias, float* __restrict__ emb)
{
    int b = blockIdx.x;
    int warp = threadIdx.x >> 5, lane = threadIdx.x & 31;
    __shared__ float hs[512];
    hs[threadIdx.x] = h[b * Hc + threadIdx.x];
    __syncthreads();
    for (int e = warp; e < 512; e += 16) {
        float s = 0.f;
        for (int c = lane; c < 512; c += 32)
            s += hs[c] * W[e * 512 + c];
        #pragma unroll
        for (int off = 16; off; off >>= 1)
            s += __shfl_down_sync(0xffffffffu, s, off);
        if (lane == 0) emb[b * Hc + e] = s + bias[e];
    }
}

// ---------------- L2 normalize * 10 ----------------
__global__ void norm_kernel(const float* __restrict__ emb, float* __restrict__ out)
{
    int b = blockIdx.x;
    int t = threadIdx.x;
    __shared__ float red[512];
    float v = emb[b * 512 + t];
    red[t] = v * v;
    __syncthreads();
    for (int s = 256; s > 0; s >>= 1) {
        if (t < s) red[t] += red[t + s];
        __syncthreads();
    }
    float scale = 10.f / sqrtf(red[0] + 1e-10f);
    out[b * 512 + t] = v * scale;
}

// ---------------- launcher ----------------
extern "C" void kernel_launch(void* const* d_in, const int* in_sizes, int n_in,
                              void* d_out, int out_size)
{
    const float* input_x = (const float*)d_in[0];
    const float* conv1_w = (const float*)d_in[1];
    const float* conv1_b = (const float*)d_in[2];
    const float* bn1_g   = (const float*)d_in[3];
    const float* bn1_b   = (const float*)d_in[4];
    const float* conv2_w = (const float*)d_in[5];
    const float* conv2_b = (const float*)d_in[6];
    const float* bn2_g   = (const float*)d_in[7];
    const float* bn2_b   = (const float*)d_in[8];
    const float* conv3_w = (const float*)d_in[9];
    const float* conv3_b = (const float*)d_in[10];
    const float* bn3_g   = (const float*)d_in[11];
    const float* bn3_b   = (const float*)d_in[12];
    const float* lin4_w  = (const float*)d_in[13];
    const float* lin4_b  = (const float*)d_in[14];
    const float* bn4_g   = (const float*)d_in[15];
    const float* bn4_b   = (const float*)d_in[16];
    const float* lin5_w  = (const float*)d_in[17];
    const float* lin5_b  = (const float*)d_in[18];
    const float* bn5_g   = (const float*)d_in[19];
    const float* bn5_b   = (const float*)d_in[20];
    const float* bot_w   = (const float*)d_in[21];
    const float* bot_b   = (const float*)d_in[22];
    const float* bnb_g   = (const float*)d_in[23];
    const float* bnb_b   = (const float*)d_in[24];
    const float* emb_w   = (const float*)d_in[25];
    const float* emb_b   = (const float*)d_in[26];
    float* out = (float*)d_out;

    float *pX0, *pA, *pB, *pX5, *pM, *pZero, *pHn, *pEmb;
    float *pSc, *pSh, *pSc4, *pSh4, *pSc5, *pSh5;
    cudaGetSymbolAddress((void**)&pX0,  g_x0);
    cudaGetSymbolAddress((void**)&pA,   g_bufA);
    cudaGetSymbolAddress((void**)&pB,   g_bufB);
    cudaGetSymbolAddress((void**)&pX5,  g_x5);
    cudaGetSymbolAddress((void**)&pM,   g_M);
    cudaGetSymbolAddress((void**)&pZero,g_zero);
    cudaGetSymbolAddress((void**)&pHn,  g_hn);
    cudaGetSymbolAddress((void**)&pEmb, g_emb);
    cudaGetSymbolAddress((void**)&pSc,  g_scale);
    cudaGetSymbolAddress((void**)&pSh,  g_shift);
    cudaGetSymbolAddress((void**)&pSc4, g_scale4);
    cudaGetSymbolAddress((void**)&pSh4, g_shift4);
    cudaGetSymbolAddress((void**)&pSc5, g_scale5);
    cudaGetSymbolAddress((void**)&pSh5, g_shift5);

    transpose_kernel<<<(Bz * T0 * F0c + 255) / 256, 256>>>(input_x, pX0);

    // conv1: C=40,KW=5,dil=1, T 400->396, CK=200, N=6336
    conv_gemm_f16k16<5,1,0,true><<<dim3(99, 4, 1), 256>>>(
        conv1_w, conv1_b, pX0, pA, nullptr, nullptr, nullptr, nullptr,
        40, 400, 396, 200, 6336, 0, 0, 0);
    bn_finalize<<<1, 512>>>(bn1_g, bn1_b, pSc, pSh, 1.f / 6336.f);

    // conv2: C=512,KW=3,dil=2, T 396->392, CK=1536, N=6272
    conv_gemm_f16k16<3,2,1,true><<<dim3(98, 4, 1), 256>>>(
        conv2_w, conv2_b, pA, pB, nullptr, nullptr, pSc, pSh,
        512, 396, 392, 1536, 6272, 0, 0, 0);
    bn_finalize<<<1, 512>>>(bn2_g, bn2_b, pSc, pSh, 1.f / 6272.f);

    // conv3: C=512,KW=3,dil=4, T 392->384, CK=1536, N=6144
    conv_gemm_f16k16<3,4,1,true><<<dim3(96, 4, 1), 256>>>(
        conv3_w, conv3_b, pB, pA, nullptr, nullptr, pSc, pSh,
        512, 392, 384, 1536, 6144, 0, 0, 0);
    bn_finalize<<<1, 512>>>(bn3_g, bn3_b, pSc, pSh, 1.f / 6144.f);

    // lin4: pointwise 512->512, T=384, CK=512, N=6144
    conv_gemm_f16k16<1,1,1,true><<<dim3(96, 4, 1), 256>>>(
        lin4_w, lin4_b, pA, pB, nullptr, nullptr, pSc, pSh,
        512, 384, 384, 512, 6144, 0, 0, 0);
    bn_finalize<<<1, 512>>>(bn4_g, bn4_b, pSc4, pSh4, 1.f / 6144.f);

    // lin5: BN4 applied on load (x4 raw in pB) -> x5 raw
    conv_gemm_f16k16<1,1,1,true><<<dim3(96, 4, 1), 256>>>(
        lin5_w, lin5_b, pB, pX5, nullptr, nullptr, pSc4, pSh4,
        512, 384, 384, 512, 6144, 0, 0, 0);
    bn_finalize<<<1, 512>>>(bn5_g, bn5_b, pSc5, pSh5, 1.f / 6144.f);

    // pooling: M[b,i,j] = sum_t bn4(x4)[b,i,t]*bn5(x5)[b,j,t]
    conv_gemm_f16k16<1,1,2,false><<<dim3(8, 4, 16), 256>>>(
        pX5, pZero, pB, pM, pSc5, pSh5, pSc4, pSh4,
        384, 1, 1, 384, 512, Hc * T3c, Hc * T3c, Kbot);

    // bottleneck: stream 512MB of bot_w once
    zero_h<<<16, 512>>>();
    bottleneck<<<dim3(16, 32), 512>>>(bot_w);

    bn2d_relu<<<1, 512>>>(bot_b, bnb_g, bnb_b);
    emb_kernel<<<16, 512>>>(pHn, emb_w, emb_b, pEmb);
    norm_kernel<<<16, 512>>>(pEmb, out);
}

// round 10
// speedup vs baseline: 1.0090x; 1.0090x over previous
#include <cuda_runtime.h>
#include <cuda_fp16.h>
#include <math.h>
#include <stdint.h>

// ---------------- problem constants ----------------
#define Bz   16
#define T0   400
#define F0c  40
#define Hc   512
#define T1c  396
#define T3c  384
#define Kbot (Hc*Hc)   // 262144

// weight arena offsets (elements)
#define WO1 0
#define WO2 102400        // 512*200
#define WO3 888832        // +512*1536
#define WO4 1675264       // +512*1536
#define WO5 1937408       // +512*512
#define WTOT 2199552      // +512*512

// ---------------- scratch (device globals; no allocs allowed) ----------------
__device__ float g_x0[Bz*F0c*T0];
__device__ float g_bufA[Bz*Hc*T1c];          // raw fp32 GEMM outputs
__device__ uint32_t g_act[Bz*Hc*T1c];        // interleaved (lo<<16|hi) split activations
__device__ __half g_wH[WTOT];
__device__ __half g_wL[WTOT];
__device__ __half g_x5H[Bz*Hc*T3c];
__device__ __half g_x5L[Bz*Hc*T3c];
__device__ float g_M[Bz*Kbot];
__device__ float g_sum[Hc];
__device__ float g_sumsq[Hc];
__device__ float g_scale[Hc];
__device__ float g_shift[Hc];
__device__ float g_h[Bz*Hc];
__device__ float g_hn[Bz*Hc];
__device__ float g_emb[Bz*Hc];
__device__ float g_zero[Hc];

// ---------------- helpers ----------------
__device__ __forceinline__ float relu20(float v)
{
    return fminf(fmaxf(v, 0.f), 20.f);
}

__device__ __forceinline__ uint32_t f16_split_pack(float v)
{
    __half h = __float2half_rn(v);
    __half l = __float2half_rn(v - __half2float(h));
    return ((uint32_t)__half_as_ushort(l) << 16) | (uint32_t)__half_as_ushort(h);
}

__device__ __forceinline__ void mma_f16_k16(float* d, const uint32_t* a, const uint32_t* b)
{
    asm volatile(
        "mma.sync.aligned.m16n8k16.row.col.f32.f16.f16.f32 "
        "{%0,%1,%2,%3}, {%4,%5,%6,%7}, {%8,%9}, {%0,%1,%2,%3};"
        : "+f"(d[0]), "+f"(d[1]), "+f"(d[2]), "+f"(d[3])
        : "r"(a[0]), "r"(a[1]), "r"(a[2]), "r"(a[3]), "r"(b[0]), "r"(b[1]));
}

__device__ __forceinline__ void ldsm_x4(uint32_t* r, uint32_t saddr)
{
    asm volatile("ldmatrix.sync.aligned.m8n8.x4.shared.b16 {%0,%1,%2,%3}, [%4];"
        : "=r"(r[0]), "=r"(r[1]), "=r"(r[2]), "=r"(r[3]) : "r"(saddr));
}

__device__ __forceinline__ void sts_v2(uint32_t saddr, uint32_t v0, uint32_t v1)
{
    asm volatile("st.shared.v2.u32 [%0], {%1,%2};" :: "r"(saddr), "r"(v0), "r"(v1));
}

__device__ __forceinline__ void sts_v4(uint32_t saddr, uint4 v)
{
    asm volatile("st.shared.v4.u32 [%0], {%1,%2,%3,%4};"
        :: "r"(saddr), "r"(v.x), "r"(v.y), "r"(v.z), "r"(v.w));
}

// ---------------- transpose + split: [B,1,T,F] -> interleaved [B,F,T] ----------------
__global__ void transpose_split(const float* __restrict__ in, uint32_t* __restrict__ out)
{
    int idx = blockIdx.x * blockDim.x + threadIdx.x;
    if (idx >= Bz * T0 * F0c) return;
    int c = idx % F0c;
    int t = (idx / F0c) % T0;
    int b = idx / (F0c * T0);
    out[(b * F0c + c) * T0 + t] = f16_split_pack(in[idx]);
}

// ---------------- weight split: all 5 weight tensors -> hi/lo arenas ----------------
__global__ void split_weights(const float* __restrict__ w1, const float* __restrict__ w2,
                              const float* __restrict__ w3, const float* __restrict__ w4,
                              const float* __restrict__ w5)
{
    int i = blockIdx.x * blockDim.x + threadIdx.x;
    if (i >= WTOT) return;
    float v;
    if (i < WO2)      v = w1[i];
    else if (i < WO3) v = w2[i - WO2];
    else if (i < WO4) v = w3[i - WO3];
    else if (i < WO5) v = w4[i - WO4];
    else              v = w5[i - WO5];
    __half h = __float2half_rn(v);
    g_wH[i] = h;
    g_wL[i] = __float2half_rn(v - __half2float(h));
}

// ---------------- BN apply + clamp + split (uses g_scale/g_shift) ----------------
template<bool SEP>
__global__ void split_bn(const float* __restrict__ Y, uint32_t* __restrict__ dst,
                         __half* __restrict__ dH, __half* __restrict__ dL,
                         int T, int total)
{
    int idx = blockIdx.x * blockDim.x + threadIdx.x;
    if (idx >= total) return;
    int c = (idx / T) & (Hc - 1);
    float v = relu20(g_scale[c] * Y[idx] + g_shift[c]);
    __half h = __float2half_rn(v);
    __half l = __float2half_rn(v - __half2float(h));
    if (SEP) {
        dH[idx] = h;
        dL[idx] = l;
    } else {
        dst[idx] = ((uint32_t)__half_as_ushort(l) << 16) | (uint32_t)__half_as_ushort(h);
    }
}

// ---------------- FP16x3 conv-as-GEMM: pre-split operands, no loader math ----------------
// A: fp16 hi/lo planes [row][CK]. X: interleaved (lo16|hi16) uint32 plane, im2col indexed.
// acc += aH*bL + aL*bH + aH*bH. BM=128 BN=64 BK=16, 256 thr, warps 4x2, tile 32x32,
// double-buffered; row stride 12 words -> LDSM conflict-free.
#define RSTR 12
template<int KW, int DIL, bool STATS>
__global__ __launch_bounds__(256, 3)
void conv_gemm_f16k16(const __half* __restrict__ AH, const __half* __restrict__ AL,
                      const float* __restrict__ bias,
                      const uint32_t* __restrict__ X, float* __restrict__ Y,
                      int C, int Tin, int Tout, int CK, int Ntot,
                      int strideA, int strideX, int strideY)
{
    AH += (size_t)blockIdx.z * strideA;
    AL += (size_t)blockIdx.z * strideA;
    X  += (size_t)blockIdx.z * strideX;
    Y  += (size_t)blockIdx.z * strideY;

    __shared__ uint32_t AsH[2][128][RSTR];
    __shared__ uint32_t AsL[2][128][RSTR];
    __shared__ uint32_t BsH[2][64][RSTR];
    __shared__ uint32_t BsL[2][64][RSTR];

    const int tid  = threadIdx.x;
    const int lane = tid & 31;
    const int warp = tid >> 5;
    const int wm = warp >> 1;      // 0..3 (32 rows each)
    const int wn = warp & 1;       // 0..1 (32 cols each)
    const int oBase = blockIdx.y * 128;
    const int nBase = blockIdx.x * 64;

    float acc[2][4][4];
    #pragma unroll
    for (int i = 0; i < 2; i++)
        #pragma unroll
        for (int j = 0; j < 4; j++)
            #pragma unroll
            for (int r = 0; r < 4; r++) acc[i][j][r] = 0.f;

    // A loader: row = tid>>1; half-cols c0..c0+7 where c0 = (tid&1)*8 -> smem words c0/2..c0/2+3
    const int aRow = tid >> 1;
    const int aC0  = (tid & 1) * 8;
    // B loader: n = tid&63, k elements bG*4..+3 -> smem words bG*2, bG*2+1
    const int bN  = tid & 63;
    const int bG  = tid >> 6;

    const int nIdx = nBase + bN;
    const bool nValid = (nIdx < Ntot);
    int nb = 0, nt0 = 0;
    if (nValid) { nb = nIdx / Tout; nt0 = nIdx - nb * Tout; }
    const uint32_t* Xbase = X + ((size_t)nb * C) * Tin + nt0;
    const __half* ArowH = AH + (size_t)(oBase + aRow) * CK + aC0;
    const __half* ArowL = AL + (size_t)(oBase + aRow) * CK + aC0;

    const uint32_t baseAH = (uint32_t)__cvta_generic_to_shared(&AsH[0][0][0]);
    const uint32_t baseAL = (uint32_t)__cvta_generic_to_shared(&AsL[0][0][0]);
    const uint32_t baseBH = (uint32_t)__cvta_generic_to_shared(&BsH[0][0][0]);
    const uint32_t baseBL = (uint32_t)__cvta_generic_to_shared(&BsL[0][0][0]);
    const uint32_t bufA = 128 * RSTR * 4;
    const uint32_t bufB = 64 * RSTR * 4;

    const uint32_t stA = (aRow * RSTR + (tid & 1) * 4) * 4;
    const uint32_t stB = (bN * RSTR + bG * 2) * 4;

    // LDSM offsets (same mapping as before)
    const int aFragRow = (lane & 7) + ((lane >> 3) & 1) * 8;
    const int aFragWord = (lane >> 4) * 4;
    const uint32_t ldA0 = ((wm * 32 + aFragRow) * RSTR + aFragWord) * 4;
    const int bFragRow = (lane & 7) + ((lane >> 4) << 3);
    const int bFragWord = ((lane >> 3) & 1) * 4;
    const uint32_t ldB0 = ((wn * 32 + bFragRow) * RSTR + bFragWord) * 4;

    uint4 paH, paL;
    uint32_t pbw[4];

    // ---- prefetch k0 = 0 ----
    {
        if (aC0 < CK) {
            paH = *(const uint4*)(ArowH);
            paL = *(const uint4*)(ArowL);
        } else {
            paH = make_uint4(0, 0, 0, 0);
            paL = make_uint4(0, 0, 0, 0);
        }
        #pragma unroll
        for (int p = 0; p < 4; p++) {
            int kkg = bG * 4 + p;
            uint32_t v = 0;
            if (nValid && kkg < CK) {
                int c = kkg / KW;
                int kw = kkg - c * KW;
                v = Xbase[c * Tin + kw * DIL];
            }
            pbw[p] = v;
        }
    }

    const int nSteps = (CK + 15) >> 4;
    int pbuf = 0;
    for (int s = 0; s < nSteps; s++) {
        // stage current k16 tile
        {
            const uint32_t offA = pbuf * bufA;
            const uint32_t offB = pbuf * bufB;
            sts_v4(baseAH + offA + stA, paH);
            sts_v4(baseAL + offA + stA, paL);
            uint32_t h0 = __byte_perm(pbw[0], pbw[1], 0x5410);
            uint32_t h1 = __byte_perm(pbw[2], pbw[3], 0x5410);
            uint32_t l0 = __byte_perm(pbw[0], pbw[1], 0x7632);
            uint32_t l1 = __byte_perm(pbw[2], pbw[3], 0x7632);
            sts_v2(baseBH + offB + stB, h0, h1);
            sts_v2(baseBL + offB + stB, l0, l1);
        }
        __syncthreads();

        // prefetch next k16 tile
        if (s + 1 < nSteps) {
            int k0 = (s + 1) * 16;
            if (k0 + aC0 < CK) {
                paH = *(const uint4*)(ArowH + k0);
                paL = *(const uint4*)(ArowL + k0);
            } else {
                paH = make_uint4(0, 0, 0, 0);
                paL = make_uint4(0, 0, 0, 0);
            }
            #pragma unroll
            for (int p = 0; p < 4; p++) {
                int kkg = k0 + bG * 4 + p;
                uint32_t v = 0;
                if (nValid && kkg < CK) {
                    int c = kkg / KW;
                    int kw = kkg - c * KW;
                    v = Xbase[c * Tin + kw * DIL];
                }
                pbw[p] = v;
            }
        }

        // fragment loads + MMA
        {
            const uint32_t offA = pbuf * bufA;
            const uint32_t offB = pbuf * bufB;
            uint32_t bHf[8], bLf[8];
            ldsm_x4(bHf,     baseBH + offB + ldB0);
            ldsm_x4(bHf + 4, baseBH + offB + ldB0 + 16 * RSTR * 4);
            ldsm_x4(bLf,     baseBL + offB + ldB0);
            ldsm_x4(bLf + 4, baseBL + offB + ldB0 + 16 * RSTR * 4);
            #pragma unroll
            for (int mt = 0; mt < 2; mt++) {
                const uint32_t mtOff = mt * 16 * RSTR * 4;
                uint32_t aHf[4], aLf[4];
                ldsm_x4(aHf, baseAH + offA + ldA0 + mtOff);
                ldsm_x4(aLf, baseAL + offA + ldA0 + mtOff);
                #pragma unroll
                for (int nt = 0; nt < 4; nt++) {
                    mma_f16_k16(acc[mt][nt], aHf, bLf + nt * 2);
                    mma_f16_k16(acc[mt][nt], aLf, bHf + nt * 2);
                    mma_f16_k16(acc[mt][nt], aHf, bHf + nt * 2);
                }
            }
        }

        pbuf ^= 1;
    }

    // epilogue
    #pragma unroll
    for (int mt = 0; mt < 2; mt++) {
        int row0 = oBase + wm * 32 + mt * 16 + (lane >> 2);
        float b0 = bias[row0];
        float b1 = bias[row0 + 8];
        float s0 = 0.f, q0 = 0.f, s1 = 0.f, q1 = 0.f;
        #pragma unroll
        for (int nt = 0; nt < 4; nt++) {
            int col0 = nBase + wn * 32 + nt * 8 + (lane & 3) * 2;
            #pragma unroll
            for (int cc = 0; cc < 2; cc++) {
                int col = col0 + cc;
                if (col < Ntot) {
                    float v0 = acc[mt][nt][cc]     + b0;
                    float v1 = acc[mt][nt][2 + cc] + b1;
                    int b = col / Tout;
                    int t = col - b * Tout;
                    size_t base = ((size_t)b * Hc) * Tout + t;
                    Y[base + (size_t)row0 * Tout]       = v0;
                    Y[base + (size_t)(row0 + 8) * Tout] = v1;
                    if (STATS) {
                        s0 += v0; q0 += v0 * v0;
                        s1 += v1; q1 += v1 * v1;
                    }
                }
            }
        }
        if (STATS) {
            #pragma unroll
            for (int off = 2; off >= 1; off >>= 1) {
                s0 += __shfl_down_sync(0xffffffffu, s0, off);
                q0 += __shfl_down_sync(0xffffffffu, q0, off);
                s1 += __shfl_down_sync(0xffffffffu, s1, off);
                q1 += __shfl_down_sync(0xffffffffu, q1, off);
            }
            if ((lane & 3) == 0) {
                atomicAdd(&g_sum[row0], s0);
                atomicAdd(&g_sumsq[row0], q0);
                atomicAdd(&g_sum[row0 + 8], s1);
                atomicAdd(&g_sumsq[row0 + 8], q1);
            }
        }
    }
}

// ---------------- BN finalize ----------------
__global__ void bn_finalize(const float* __restrict__ g, const float* __restrict__ be,
                            float invN)
{
    int c = threadIdx.x;   // 512
    float s = g_sum[c], q = g_sumsq[c];
    float m = s * invN;
    float var = q * invN - m * m;
    float a = g[c] * rsqrtf(var + 1e-5f);
    g_scale[c] = a;
    g_shift[c] = be[c] - a * m;
    g_sum[c] = 0.f;
    g_sumsq[c] = 0.f;
}

// ---------------- bottleneck ----------------
__global__ void zero_h()
{
    g_h[blockIdx.x * blockDim.x + threadIdx.x] = 0.f;
}

__global__ __launch_bounds__(512)
void bottleneck(const float* __restrict__ W)
{
    __shared__ float Ms[Bz][512];
    int warp = threadIdx.x >> 5, lane = threadIdx.x & 31;
    int o0 = blockIdx.x * 32 + warp * 2;
    int k0 = blockIdx.y * (Kbot / 32);

    float acc0[16], acc1[16];
    #pragma unroll
    for (int b = 0; b < 16; b++) { acc0[b] = 0.f; acc1[b] = 0.f; }

    for (int kt = 0; kt < Kbot / 32; kt += 512) {
        __syncthreads();
        #pragma unroll
        for (int i = 0; i < 16; i++) {
            int idx = threadIdx.x + i * 512;
            int b = idx >> 9, kk = idx & 511;
            Ms[b][kk] = g_M[b * Kbot + k0 + kt + kk];
        }
        __syncthreads();
        const float* w0p = W + (size_t)o0 * Kbot + k0 + kt;
        const float* w1p = w0p + Kbot;
        #pragma unroll
        for (int kk = lane * 4; kk < 512; kk += 128) {
            float4 w0 = *(const float4*)(w0p + kk);
            float4 w1 = *(const float4*)(w1p + kk);
            #pragma unroll
            for (int b = 0; b < 16; b++) {
                float4 m = *(const float4*)&Ms[b][kk];
                acc0[b] += w0.x * m.x + w0.y * m.y + w0.z * m.z + w0.w * m.w;
                acc1[b] += w1.x * m.x + w1.y * m.y + w1.z * m.z + w1.w * m.w;
            }
        }
    }
    #pragma unroll
    for (int b = 0; b < 16; b++) {
        float v0 = acc0[b], v1 = acc1[b];
        #pragma unroll
        for (int off = 16; off; off >>= 1) {
            v0 += __shfl_down_sync(0xffffffffu, v0, off);
            v1 += __shfl_down_sync(0xffffffffu, v1, off);
        }
        if (lane == 0) {
            atomicAdd(&g_h[b * Hc + o0], v0);
            atomicAdd(&g_h[b * Hc + o0 + 1], v1);
        }
    }
}

// ---------------- BN over batch + relu20 ----------------
__global__ void bn2d_relu(const float* __restrict__ bot_b, const float* __restrict__ gg,
                          const float* __restrict__ gb)
{
    int o = threadIdx.x;
    float v[16];
    float s = 0.f, sq = 0.f;
    #pragma unroll
    for (int b = 0; b < 16; b++) {
        float x = g_h[b * Hc + o] + bot_b[o];
        v[b] = x; s += x; sq += x * x;
    }
    float m = s * (1.f / 16.f);
    float var = sq * (1.f / 16.f) - m * m;
    float a = gg[o] * rsqrtf(var + 1e-5f);
    float d = gb[o] - a * m;
    #pragma unroll
    for (int b = 0; b < 16; b++) {
        float z = a * v[b] + d;
        g_hn[b * Hc + o] = fminf(fmaxf(z, 0.f), 20.f);
    }
}

// ---------------- embedding GEMV + bias ----------------
__global__ void emb_kernel(const float* __restrict__ h, const float* __restrict__ W,
                           const float* __restrict__ bias, float* __restrict__ emb)
{
    int b = blockIdx.x;
    int warp = threadIdx.x >> 5, lane = threadIdx.x & 31;
    __shared__ float hs[512];
    hs[threadIdx.x] = h[b * Hc + threadIdx.x];
    __syncthreads();
    for (int e = warp; e < 512; e += 16) {
        float s = 0.f;
        for (int c = lane; c < 512; c += 32)
            s += hs[c] * W[e * 512 + c];
        #pragma unroll
        for (int off = 16; off; off >>= 1)
            s += __shfl_down_sync(0xffffffffu, s, off);
        if (lane == 0) emb[b * Hc + e] = s + bias[e];
    }
}

// ---------------- L2 normalize * 10 ----------------
__global__ void norm_kernel(const float* __restrict__ emb, float* __restrict__ out)
{
    int b = blockIdx.x;
    int t = threadIdx.x;
    __shared__ float red[512];
    float v = emb[b * 512 + t];
    red[t] = v * v;
    __syncthreads();
    for (int s = 256; s > 0; s >>= 1) {
        if (t < s) red[t] += red[t + s];
        __syncthreads();
    }
    float scale = 10.f / sqrtf(red[0] + 1e-10f);
    out[b * 512 + t] = v * scale;
}

// ---------------- launcher ----------------
extern "C" void kernel_launch(void* const* d_in, const int* in_sizes, int n_in,
                              void* d_out, int out_size)
{
    const float* input_x = (const float*)d_in[0];
    const float* conv1_w = (const float*)d_in[1];
    const float* conv1_b = (const float*)d_in[2];
    const float* bn1_g   = (const float*)d_in[3];
    const float* bn1_b   = (const float*)d_in[4];
    const float* conv2_w = (const float*)d_in[5];
    const float* conv2_b = (const float*)d_in[6];
    const float* bn2_g   = (const float*)d_in[7];
    const float* bn2_b   = (const float*)d_in[8];
    const float* conv3_w = (const float*)d_in[9];
    const float* conv3_b = (const float*)d_in[10];
    const float* bn3_g   = (const float*)d_in[11];
    const float* bn3_b   = (const float*)d_in[12];
    const float* lin4_w  = (const float*)d_in[13];
    const float* lin4_b  = (const float*)d_in[14];
    const float* bn4_g   = (const float*)d_in[15];
    const float* bn4_b   = (const float*)d_in[16];
    const float* lin5_w  = (const float*)d_in[17];
    const float* lin5_b  = (const float*)d_in[18];
    const float* bn5_g   = (const float*)d_in[19];
    const float* bn5_b   = (const float*)d_in[20];
    const float* bot_w   = (const float*)d_in[21];
    const float* bot_b   = (const float*)d_in[22];
    const float* bnb_g   = (const float*)d_in[23];
    const float* bnb_b   = (const float*)d_in[24];
    const float* emb_w   = (const float*)d_in[25];
    const float* emb_b   = (const float*)d_in[26];
    float* out = (float*)d_out;

    float *pA, *pM, *pZero, *pHn, *pEmb;
    uint32_t *pAct;
    __half *pWH, *pWL, *pX5H, *pX5L;
    cudaGetSymbolAddress((void**)&pA,   g_bufA);
    cudaGetSymbolAddress((void**)&pAct, g_act);
    cudaGetSymbolAddress((void**)&pWH,  g_wH);
    cudaGetSymbolAddress((void**)&pWL,  g_wL);
    cudaGetSymbolAddress((void**)&pX5H, g_x5H);
    cudaGetSymbolAddress((void**)&pX5L, g_x5L);
    cudaGetSymbolAddress((void**)&pM,   g_M);
    cudaGetSymbolAddress((void**)&pZero,g_zero);
    cudaGetSymbolAddress((void**)&pHn,  g_hn);
    cudaGetSymbolAddress((void**)&pEmb, g_emb);

    // upfront: weight split + input transpose/split
    split_weights<<<(WTOT + 255) / 256, 256>>>(conv1_w, conv2_w, conv3_w, lin4_w, lin5_w);
    transpose_split<<<(Bz * T0 * F0c + 255) / 256, 256>>>(input_x, pAct);

    // conv1: CK=200, T 400->396, N=6336
    conv_gemm_f16k16<5,1,true><<<dim3(99, 4, 1), 256>>>(
        pWH + WO1, pWL + WO1, conv1_b, pAct, pA,
        40, 400, 396, 200, 6336, 0, 0, 0);
    bn_finalize<<<1, 512>>>(bn1_g, bn1_b, 1.f / 6336.f);
    split_bn<false><<<(Bz * Hc * 396 + 255) / 256, 256>>>(pA, pAct, nullptr, nullptr,
                                                          396, Bz * Hc * 396);

    // conv2: CK=1536, T 396->392, N=6272
    conv_gemm_f16k16<3,2,true><<<dim3(98, 4, 1), 256>>>(
        pWH + WO2, pWL + WO2, conv2_b, pAct, pA,
        512, 396, 392, 1536, 6272, 0, 0, 0);
    bn_finalize<<<1, 512>>>(bn2_g, bn2_b, 1.f / 6272.f);
    split_bn<false><<<(Bz * Hc * 392 + 255) / 256, 256>>>(pA, pAct, nullptr, nullptr,
                                                          392, Bz * Hc * 392);

    // conv3: CK=1536, T 392->384, N=6144
    conv_gemm_f16k16<3,4,true><<<dim3(96, 4, 1), 256>>>(
        pWH + WO3, pWL + WO3, conv3_b, pAct, pA,
        512, 392, 384, 1536, 6144, 0, 0, 0);
    bn_finalize<<<1, 512>>>(bn3_g, bn3_b, 1.f / 6144.f);
    split_bn<false><<<(Bz * Hc * 384 + 255) / 256, 256>>>(pA, pAct, nullptr, nullptr,
                                                          384, Bz * Hc * 384);

    // lin4: CK=512, T=384, N=6144
    conv_gemm_f16k16<1,1,true><<<dim3(96, 4, 1), 256>>>(
        pWH + WO4, pWL + WO4, lin4_b, pAct, pA,
        512, 384, 384, 512, 6144, 0, 0, 0);
    bn_finalize<<<1, 512>>>(bn4_g, bn4_b, 1.f / 6144.f);
    split_bn<false><<<(Bz * Hc * 384 + 255) / 256, 256>>>(pA, pAct, nullptr, nullptr,
                                                          384, Bz * Hc * 384);   // x4 split

    // lin5: reads x4 split -> raw x5
    conv_gemm_f16k16<1,1,true><<<dim3(96, 4, 1), 256>>>(
        pWH + WO5, pWL + WO5, lin5_b, pAct, pA,
        512, 384, 384, 512, 6144, 0, 0, 0);
    bn_finalize<<<1, 512>>>(bn5_g, bn5_b, 1.f / 6144.f);
    split_bn<true><<<(Bz * Hc * 384 + 255) / 256, 256>>>(pA, nullptr, pX5H, pX5L,
                                                         384, Bz * Hc * 384);    // x5 planes

    // pooling: M[b,i,j] = sum_t x4n[b,i,t]*x5n[b,j,t]; A = x5 planes, X = x4 interleaved
    conv_gemm_f16k16<1,1,false><<<dim3(8, 4, 16), 256>>>(
        pX5H, pX5L, pZero, pAct, pM,
        384, 1, 1, 384, 512, Hc * T3c, Hc * T3c, Kbot);

    // bottleneck: stream 512MB of bot_w once
    zero_h<<<16, 512>>>();
    bottleneck<<<dim3(16, 32), 512>>>(bot_w);

    bn2d_relu<<<1, 512>>>(bot_b, bnb_g, bnb_b);
    emb_kernel<<<16, 512>>>(pHn, emb_w, emb_b, pEmb);
    norm_kernel<<<16, 512>>>(pEmb, out);
}

// round 11
// speedup vs baseline: 1.1044x; 1.0945x over previous
#include <cuda_runtime.h>
#include <cuda_fp16.h>
#include <math.h>
#include <stdint.h>

// ---------------- problem constants ----------------
#define Bz   16
#define T0   400
#define F0c  40
#define Hc   512
#define T1c  396
#define T3c  384
#define Kbot (Hc*Hc)   // 262144

// weight arena offsets (elements)
#define WO1 0
#define WO2 102400        // 512*200
#define WO3 888832        // +512*1536
#define WO4 1675264       // +512*1536
#define WO5 1937408       // +512*512
#define WTOT 2199552      // +512*512

// ---------------- scratch (device globals; no allocs allowed) ----------------
__device__ float g_bufA[Bz*Hc*T1c];          // raw fp32 GEMM outputs
__device__ uint32_t g_act[Bz*Hc*T1c];        // interleaved (lo<<16|hi) split activations
__device__ __half g_wH[WTOT];
__device__ __half g_wL[WTOT];
__device__ __half g_x5H[Bz*Hc*T3c];
__device__ __half g_x5L[Bz*Hc*T3c];
__device__ uint32_t g_M[Bz*Kbot];            // pooled matrices, packed (lo16|hi16)
__device__ float g_sum[Hc];
__device__ float g_sumsq[Hc];
__device__ float g_scale[Hc];
__device__ float g_shift[Hc];
__device__ float g_h[Bz*Hc];
__device__ float g_hn[Bz*Hc];
__device__ float g_emb[Bz*Hc];
__device__ float g_zero[Hc];

// ---------------- helpers ----------------
__device__ __forceinline__ float relu20(float v)
{
    return fminf(fmaxf(v, 0.f), 20.f);
}

__device__ __forceinline__ uint32_t f16_split_pack(float v)
{
    __half h = __float2half_rn(v);
    __half l = __float2half_rn(v - __half2float(h));
    return ((uint32_t)__half_as_ushort(l) << 16) | (uint32_t)__half_as_ushort(h);
}

// split two floats into packed fp16x2 hi word + fp16x2 lo word
__device__ __forceinline__ void f16_split2(float x0, float x1, uint32_t& hw, uint32_t& lw)
{
    __half2 h = __floats2half2_rn(x0, x1);
    float2 hf = __half22float2(h);
    __half2 l = __floats2half2_rn(x0 - hf.x, x1 - hf.y);
    hw = *(uint32_t*)&h;
    lw = *(uint32_t*)&l;
}

__device__ __forceinline__ void mma_f16_k16(float* d, const uint32_t* a, const uint32_t* b)
{
    asm volatile(
        "mma.sync.aligned.m16n8k16.row.col.f32.f16.f16.f32 "
        "{%0,%1,%2,%3}, {%4,%5,%6,%7}, {%8,%9}, {%0,%1,%2,%3};"
        : "+f"(d[0]), "+f"(d[1]), "+f"(d[2]), "+f"(d[3])
        : "r"(a[0]), "r"(a[1]), "r"(a[2]), "r"(a[3]), "r"(b[0]), "r"(b[1]));
}

__device__ __forceinline__ void ldsm_x4(uint32_t* r, uint32_t saddr)
{
    asm volatile("ldmatrix.sync.aligned.m8n8.x4.shared.b16 {%0,%1,%2,%3}, [%4];"
        : "=r"(r[0]), "=r"(r[1]), "=r"(r[2]), "=r"(r[3]) : "r"(saddr));
}

__device__ __forceinline__ void sts_v2(uint32_t saddr, uint32_t v0, uint32_t v1)
{
    asm volatile("st.shared.v2.u32 [%0], {%1,%2};" :: "r"(saddr), "r"(v0), "r"(v1));
}

__device__ __forceinline__ void sts_v4(uint32_t saddr, uint4 v)
{
    asm volatile("st.shared.v4.u32 [%0], {%1,%2,%3,%4};"
        :: "r"(saddr), "r"(v.x), "r"(v.y), "r"(v.z), "r"(v.w));
}

// ---------------- transpose + split: [B,1,T,F] -> interleaved [B,F,T] ----------------
__global__ void transpose_split(const float* __restrict__ in, uint32_t* __restrict__ out)
{
    int idx = blockIdx.x * blockDim.x + threadIdx.x;
    if (idx >= Bz * T0 * F0c) return;
    int c = idx % F0c;
    int t = (idx / F0c) % T0;
    int b = idx / (F0c * T0);
    out[(b * F0c + c) * T0 + t] = f16_split_pack(in[idx]);
}

// ---------------- weight split ----------------
__global__ void split_weights(const float* __restrict__ w1, const float* __restrict__ w2,
                              const float* __restrict__ w3, const float* __restrict__ w4,
                              const float* __restrict__ w5)
{
    int i = blockIdx.x * blockDim.x + threadIdx.x;
    if (i >= WTOT) return;
    float v;
    if (i < WO2)      v = w1[i];
    else if (i < WO3) v = w2[i - WO2];
    else if (i < WO4) v = w3[i - WO3];
    else if (i < WO5) v = w4[i - WO4];
    else              v = w5[i - WO5];
    __half h = __float2half_rn(v);
    g_wH[i] = h;
    g_wL[i] = __float2half_rn(v - __half2float(h));
}

// ---------------- BN apply + clamp + split ----------------
template<bool SEP>
__global__ void split_bn(const float* __restrict__ Y, uint32_t* __restrict__ dst,
                         __half* __restrict__ dH, __half* __restrict__ dL,
                         int T, int total)
{
    int idx = blockIdx.x * blockDim.x + threadIdx.x;
    if (idx >= total) return;
    int c = (idx / T) & (Hc - 1);
    float v = relu20(g_scale[c] * Y[idx] + g_shift[c]);
    __half h = __float2half_rn(v);
    __half l = __float2half_rn(v - __half2float(h));
    if (SEP) {
        dH[idx] = h;
        dL[idx] = l;
    } else {
        dst[idx] = ((uint32_t)__half_as_ushort(l) << 16) | (uint32_t)__half_as_ushort(h);
    }
}

// ---------------- FP16x3 conv-as-GEMM: pre-split operands ----------------
// PACK: epilogue writes packed (lo|hi) uint32 instead of fp32 (for pooling -> M).
#define RSTR 12
template<int KW, int DIL, bool STATS, bool PACK>
__global__ __launch_bounds__(256, 3)
void conv_gemm_f16k16(const __half* __restrict__ AH, const __half* __restrict__ AL,
                      const float* __restrict__ bias,
                      const uint32_t* __restrict__ X, float* __restrict__ Y,
                      int C, int Tin, int Tout, int CK, int Ntot,
                      int strideA, int strideX, int strideY)
{
    AH += (size_t)blockIdx.z * strideA;
    AL += (size_t)blockIdx.z * strideA;
    X  += (size_t)blockIdx.z * strideX;
    Y  += (size_t)blockIdx.z * strideY;

    __shared__ uint32_t AsH[2][128][RSTR];
    __shared__ uint32_t AsL[2][128][RSTR];
    __shared__ uint32_t BsH[2][64][RSTR];
    __shared__ uint32_t BsL[2][64][RSTR];

    const int tid  = threadIdx.x;
    const int lane = tid & 31;
    const int warp = tid >> 5;
    const int wm = warp >> 1;      // 0..3 (32 rows each)
    const int wn = warp & 1;       // 0..1 (32 cols each)
    const int oBase = blockIdx.y * 128;
    const int nBase = blockIdx.x * 64;

    float acc[2][4][4];
    #pragma unroll
    for (int i = 0; i < 2; i++)
        #pragma unroll
        for (int j = 0; j < 4; j++)
            #pragma unroll
            for (int r = 0; r < 4; r++) acc[i][j][r] = 0.f;

    const int aRow = tid >> 1;
    const int aC0  = (tid & 1) * 8;
    const int bN  = tid & 63;
    const int bG  = tid >> 6;

    const int nIdx = nBase + bN;
    const bool nValid = (nIdx < Ntot);
    int nb = 0, nt0 = 0;
    if (nValid) { nb = nIdx / Tout; nt0 = nIdx - nb * Tout; }
    const uint32_t* Xbase = X + ((size_t)nb * C) * Tin + nt0;
    const __half* ArowH = AH + (size_t)(oBase + aRow) * CK + aC0;
    const __half* ArowL = AL + (size_t)(oBase + aRow) * CK + aC0;

    const uint32_t baseAH = (uint32_t)__cvta_generic_to_shared(&AsH[0][0][0]);
    const uint32_t baseAL = (uint32_t)__cvta_generic_to_shared(&AsL[0][0][0]);
    const uint32_t baseBH = (uint32_t)__cvta_generic_to_shared(&BsH[0][0][0]);
    const uint32_t baseBL = (uint32_t)__cvta_generic_to_shared(&BsL[0][0][0]);
    const uint32_t bufA = 128 * RSTR * 4;
    const uint32_t bufB = 64 * RSTR * 4;

    const uint32_t stA = (aRow * RSTR + (tid & 1) * 4) * 4;
    const uint32_t stB = (bN * RSTR + bG * 2) * 4;

    const int aFragRow = (lane & 7) + ((lane >> 3) & 1) * 8;
    const int aFragWord = (lane >> 4) * 4;
    const uint32_t ldA0 = ((wm * 32 + aFragRow) * RSTR + aFragWord) * 4;
    const int bFragRow = (lane & 7) + ((lane >> 4) << 3);
    const int bFragWord = ((lane >> 3) & 1) * 4;
    const uint32_t ldB0 = ((wn * 32 + bFragRow) * RSTR + bFragWord) * 4;

    uint4 paH, paL;
    uint32_t pbw[4];

    // ---- prefetch k0 = 0 ----
    {
        if (aC0 < CK) {
            paH = *(const uint4*)(ArowH);
            paL = *(const uint4*)(ArowL);
        } else {
            paH = make_uint4(0, 0, 0, 0);
            paL = make_uint4(0, 0, 0, 0);
        }
        #pragma unroll
        for (int p = 0; p < 4; p++) {
            int kkg = bG * 4 + p;
            uint32_t v = 0;
            if (nValid && kkg < CK) {
                int c = kkg / KW;
                int kw = kkg - c * KW;
                v = Xbase[c * Tin + kw * DIL];
            }
            pbw[p] = v;
        }
    }

    const int nSteps = (CK + 15) >> 4;
    int pbuf = 0;
    for (int s = 0; s < nSteps; s++) {
        {
            const uint32_t offA = pbuf * bufA;
            const uint32_t offB = pbuf * bufB;
            sts_v4(baseAH + offA + stA, paH);
            sts_v4(baseAL + offA + stA, paL);
            uint32_t h0 = __byte_perm(pbw[0], pbw[1], 0x5410);
            uint32_t h1 = __byte_perm(pbw[2], pbw[3], 0x5410);
            uint32_t l0 = __byte_perm(pbw[0], pbw[1], 0x7632);
            uint32_t l1 = __byte_perm(pbw[2], pbw[3], 0x7632);
            sts_v2(baseBH + offB + stB, h0, h1);
            sts_v2(baseBL + offB + stB, l0, l1);
        }
        __syncthreads();

        if (s + 1 < nSteps) {
            int k0 = (s + 1) * 16;
            if (k0 + aC0 < CK) {
                paH = *(const uint4*)(ArowH + k0);
                paL = *(const uint4*)(ArowL + k0);
            } else {
                paH = make_uint4(0, 0, 0, 0);
                paL = make_uint4(0, 0, 0, 0);
            }
            #pragma unroll
            for (int p = 0; p < 4; p++) {
                int kkg = k0 + bG * 4 + p;
                uint32_t v = 0;
                if (nValid && kkg < CK) {
                    int c = kkg / KW;
                    int kw = kkg - c * KW;
                    v = Xbase[c * Tin + kw * DIL];
                }
                pbw[p] = v;
            }
        }

        {
            const uint32_t offA = pbuf * bufA;
            const uint32_t offB = pbuf * bufB;
            uint32_t bHf[8], bLf[8];
            ldsm_x4(bHf,     baseBH + offB + ldB0);
            ldsm_x4(bHf + 4, baseBH + offB + ldB0 + 16 * RSTR * 4);
            ldsm_x4(bLf,     baseBL + offB + ldB0);
            ldsm_x4(bLf + 4, baseBL + offB + ldB0 + 16 * RSTR * 4);
            #pragma unroll
            for (int mt = 0; mt < 2; mt++) {
                const uint32_t mtOff = mt * 16 * RSTR * 4;
                uint32_t aHf[4], aLf[4];
                ldsm_x4(aHf, baseAH + offA + ldA0 + mtOff);
                ldsm_x4(aLf, baseAL + offA + ldA0 + mtOff);
                #pragma unroll
                for (int nt = 0; nt < 4; nt++) {
                    mma_f16_k16(acc[mt][nt], aHf, bLf + nt * 2);
                    mma_f16_k16(acc[mt][nt], aLf, bHf + nt * 2);
                    mma_f16_k16(acc[mt][nt], aHf, bHf + nt * 2);
                }
            }
        }

        pbuf ^= 1;
    }

    // epilogue
    #pragma unroll
    for (int mt = 0; mt < 2; mt++) {
        int row0 = oBase + wm * 32 + mt * 16 + (lane >> 2);
        float b0 = bias[row0];
        float b1 = bias[row0 + 8];
        float s0 = 0.f, q0 = 0.f, s1 = 0.f, q1 = 0.f;
        #pragma unroll
        for (int nt = 0; nt < 4; nt++) {
            int col0 = nBase + wn * 32 + nt * 8 + (lane & 3) * 2;
            #pragma unroll
            for (int cc = 0; cc < 2; cc++) {
                int col = col0 + cc;
                if (col < Ntot) {
                    float v0 = acc[mt][nt][cc]     + b0;
                    float v1 = acc[mt][nt][2 + cc] + b1;
                    int b = col / Tout;
                    int t = col - b * Tout;
                    size_t base = ((size_t)b * Hc) * Tout + t;
                    if (PACK) {
                        Y[base + (size_t)row0 * Tout]       = __uint_as_float(f16_split_pack(v0));
                        Y[base + (size_t)(row0 + 8) * Tout] = __uint_as_float(f16_split_pack(v1));
                    } else {
                        Y[base + (size_t)row0 * Tout]       = v0;
                        Y[base + (size_t)(row0 + 8) * Tout] = v1;
                    }
                    if (STATS) {
                        s0 += v0; q0 += v0 * v0;
                        s1 += v1; q1 += v1 * v1;
                    }
                }
            }
        }
        if (STATS) {
            #pragma unroll
            for (int off = 2; off >= 1; off >>= 1) {
                s0 += __shfl_down_sync(0xffffffffu, s0, off);
                q0 += __shfl_down_sync(0xffffffffu, q0, off);
                s1 += __shfl_down_sync(0xffffffffu, s1, off);
                q1 += __shfl_down_sync(0xffffffffu, q1, off);
            }
            if ((lane & 3) == 0) {
                atomicAdd(&g_sum[row0], s0);
                atomicAdd(&g_sumsq[row0], q0);
                atomicAdd(&g_sum[row0 + 8], s1);
                atomicAdd(&g_sumsq[row0 + 8], q1);
            }
        }
    }
}

// ---------------- BN finalize ----------------
__global__ void bn_finalize(const float* __restrict__ g, const float* __restrict__ be,
                            float invN)
{
    int c = threadIdx.x;   // 512
    float s = g_sum[c], q = g_sumsq[c];
    float m = s * invN;
    float var = q * invN - m * m;
    float a = g[c] * rsqrtf(var + 1e-5f);
    g_scale[c] = a;
    g_shift[c] = be[c] - a * m;
    g_sum[c] = 0.f;
    g_sumsq[c] = 0.f;
}

// ---------------- bottleneck (tensor-core, fp16x3) ----------------
// h[16,512] = M16[16,K] @ W[512,K]^T, K=262144.
// A = packed-split M (LDG + PRMT -> frags), B = fp32 W split on the fly. No smem.
// Grid (8 o-groups of 64, 64 k-chunks of 4096); warp = 8 o's; atomic f32 epilogue.
__global__ void zero_h()
{
    g_h[blockIdx.x * blockDim.x + threadIdx.x] = 0.f;
}

__global__ __launch_bounds__(256)
void bottleneck_tc(const float* __restrict__ W)
{
    const int lane = threadIdx.x & 31;
    const int warp = threadIdx.x >> 5;
    const int o0 = blockIdx.x * 64 + warp * 8;     // this warp's 8 output cols
    const int kb = blockIdx.y * 4096;

    const int r  = lane >> 2;          // 0..7 (A row / B n)
    const int kq = (lane & 3) * 2;     // k pair offset

    const uint32_t* m0 = g_M + (size_t)r * Kbot + kb + kq;
    const uint32_t* m1 = g_M + (size_t)(r + 8) * Kbot + kb + kq;
    const float*    w0 = W + (size_t)(o0 + r) * Kbot + kb + kq;

    float acc[4] = {0.f, 0.f, 0.f, 0.f};

    #pragma unroll 2
    for (int s = 0; s < 4096; s += 16) {
        uint2 u0 = *(const uint2*)(m0 + s);        // r,   kL pair
        uint2 u2 = *(const uint2*)(m0 + s + 8);    // r,   kH pair
        uint2 u1 = *(const uint2*)(m1 + s);        // r+8, kL pair
        uint2 u3 = *(const uint2*)(m1 + s + 8);    // r+8, kH pair
        float2 wv0 = *(const float2*)(w0 + s);
        float2 wv1 = *(const float2*)(w0 + s + 8);

        uint32_t aH[4], aL[4];
        aH[0] = __byte_perm(u0.x, u0.y, 0x5410);  aL[0] = __byte_perm(u0.x, u0.y, 0x7632);
        aH[1] = __byte_perm(u1.x, u1.y, 0x5410);  aL[1] = __byte_perm(u1.x, u1.y, 0x7632);
        aH[2] = __byte_perm(u2.x, u2.y, 0x5410);  aL[2] = __byte_perm(u2.x, u2.y, 0x7632);
        aH[3] = __byte_perm(u3.x, u3.y, 0x5410);  aL[3] = __byte_perm(u3.x, u3.y, 0x7632);

        uint32_t bH[2], bL[2];
        f16_split2(wv0.x, wv0.y, bH[0], bL[0]);
        f16_split2(wv1.x, wv1.y, bH[1], bL[1]);

        mma_f16_k16(acc, aH, bL);
        mma_f16_k16(acc, aL, bH);
        mma_f16_k16(acc, aH, bH);
    }

    // D: d0=(r, c), d1=(r, c+1), d2=(r+8, c), d3=(r+8, c+1); c = kq
    int o = o0 + kq;
    atomicAdd(&g_h[r * Hc + o],           acc[0]);
    atomicAdd(&g_h[r * Hc + o + 1],       acc[1]);
    atomicAdd(&g_h[(r + 8) * Hc + o],     acc[2]);
    atomicAdd(&g_h[(r + 8) * Hc + o + 1], acc[3]);
}

// ---------------- BN over batch + relu20 ----------------
__global__ void bn2d_relu(const float* __restrict__ bot_b, const float* __restrict__ gg,
                          const float* __restrict__ gb)
{
    int o = threadIdx.x;
    float v[16];
    float s = 0.f, sq = 0.f;
    #pragma unroll
    for (int b = 0; b < 16; b++) {
        float x = g_h[b * Hc + o] + bot_b[o];
        v[b] = x; s += x; sq += x * x;
    }
    float m = s * (1.f / 16.f);
    float var = sq * (1.f / 16.f) - m * m;
    float a = gg[o] * rsqrtf(var + 1e-5f);
    float d = gb[o] - a * m;
    #pragma unroll
    for (int b = 0; b < 16; b++) {
        float z = a * v[b] + d;
        g_hn[b * Hc + o] = fminf(fmaxf(z, 0.f), 20.f);
    }
}

// ---------------- embedding GEMV + bias ----------------
__global__ void emb_kernel(const float* __restrict__ h, const float* __restrict__ W,
                           const float* __restrict__ bias, float* __restrict__ emb)
{
    int b = blockIdx.x;
    int warp = threadIdx.x >> 5, lane = threadIdx.x & 31;
    __shared__ float hs[512];
    hs[threadIdx.x] = h[b * Hc + threadIdx.x];
    __syncthreads();
    for (int e = warp; e < 512; e += 16) {
        float s = 0.f;
        for (int c = lane; c < 512; c += 32)
            s += hs[c] * W[e * 512 + c];
        #pragma unroll
        for (int off = 16; off; off >>= 1)
            s += __shfl_down_sync(0xffffffffu, s, off);
        if (lane == 0) emb[b * Hc + e] = s + bias[e];
    }
}

// ---------------- L2 normalize * 10 ----------------
__global__ void norm_kernel(const float* __restrict__ emb, float* __restrict__ out)
{
    int b = blockIdx.x;
    int t = threadIdx.x;
    __shared__ float red[512];
    float v = emb[b * 512 + t];
    red[t] = v * v;
    __syncthreads();
    for (int s = 256; s > 0; s >>= 1) {
        if (t < s) red[t] += red[t + s];
        __syncthreads();
    }
    float scale = 10.f / sqrtf(red[0] + 1e-10f);
    out[b * 512 + t] = v * scale;
}

// ---------------- launcher ----------------
extern "C" void kernel_launch(void* const* d_in, const int* in_sizes, int n_in,
                              void* d_out, int out_size)
{
    const float* input_x = (const float*)d_in[0];
    const float* conv1_w = (const float*)d_in[1];
    const float* conv1_b = (const float*)d_in[2];
    const float* bn1_g   = (const float*)d_in[3];
    const float* bn1_b   = (const float*)d_in[4];
    const float* conv2_w = (const float*)d_in[5];
    const float* conv2_b = (const float*)d_in[6];
    const float* bn2_g   = (const float*)d_in[7];
    const float* bn2_b   = (const float*)d_in[8];
    const float* conv3_w = (const float*)d_in[9];
    const float* conv3_b = (const float*)d_in[10];
    const float* bn3_g   = (const float*)d_in[11];
    const float* bn3_b   = (const float*)d_in[12];
    const float* lin4_w  = (const float*)d_in[13];
    const float* lin4_b  = (const float*)d_in[14];
    const float* bn4_g   = (const float*)d_in[15];
    const float* bn4_b   = (const float*)d_in[16];
    const float* lin5_w  = (const float*)d_in[17];
    const float* lin5_b  = (const float*)d_in[18];
    const float* bn5_g   = (const float*)d_in[19];
    const float* bn5_b   = (const float*)d_in[20];
    const float* bot_w   = (const float*)d_in[21];
    const float* bot_b   = (const float*)d_in[22];
    const float* bnb_g   = (const float*)d_in[23];
    const float* bnb_b   = (const float*)d_in[24];
    const float* emb_w   = (const float*)d_in[25];
    const float* emb_b   = (const float*)d_in[26];
    float* out = (float*)d_out;

    float *pA, *pZero, *pHn, *pEmb, *pMf;
    uint32_t *pAct;
    __half *pWH, *pWL, *pX5H, *pX5L;
    cudaGetSymbolAddress((void**)&pA,   g_bufA);
    cudaGetSymbolAddress((void**)&pAct, g_act);
    cudaGetSymbolAddress((void**)&pWH,  g_wH);
    cudaGetSymbolAddress((void**)&pWL,  g_wL);
    cudaGetSymbolAddress((void**)&pX5H, g_x5H);
    cudaGetSymbolAddress((void**)&pX5L, g_x5L);
    cudaGetSymbolAddress((void**)&pMf,  g_M);
    cudaGetSymbolAddress((void**)&pZero,g_zero);
    cudaGetSymbolAddress((void**)&pHn,  g_hn);
    cudaGetSymbolAddress((void**)&pEmb, g_emb);

    // upfront: weight split + input transpose/split
    split_weights<<<(WTOT + 255) / 256, 256>>>(conv1_w, conv2_w, conv3_w, lin4_w, lin5_w);
    transpose_split<<<(Bz * T0 * F0c + 255) / 256, 256>>>(input_x, pAct);

    // conv1: CK=200, T 400->396, N=6336
    conv_gemm_f16k16<5,1,true,false><<<dim3(99, 4, 1), 256>>>(
        pWH + WO1, pWL + WO1, conv1_b, pAct, pA,
        40, 400, 396, 200, 6336, 0, 0, 0);
    bn_finalize<<<1, 512>>>(bn1_g, bn1_b, 1.f / 6336.f);
    split_bn<false><<<(Bz * Hc * 396 + 255) / 256, 256>>>(pA, pAct, nullptr, nullptr,
                                                          396, Bz * Hc * 396);

    // conv2: CK=1536, T 396->392, N=6272
    conv_gemm_f16k16<3,2,true,false><<<dim3(98, 4, 1), 256>>>(
        pWH + WO2, pWL + WO2, conv2_b, pAct, pA,
        512, 396, 392, 1536, 6272, 0, 0, 0);
    bn_finalize<<<1, 512>>>(bn2_g, bn2_b, 1.f / 6272.f);
    split_bn<false><<<(Bz * Hc * 392 + 255) / 256, 256>>>(pA, pAct, nullptr, nullptr,
                                                          392, Bz * Hc * 392);

    // conv3: CK=1536, T 392->384, N=6144
    conv_gemm_f16k16<3,4,true,false><<<dim3(96, 4, 1), 256>>>(
        pWH + WO3, pWL + WO3, conv3_b, pAct, pA,
        512, 392, 384, 1536, 6144, 0, 0, 0);
    bn_finalize<<<1, 512>>>(bn3_g, bn3_b, 1.f / 6144.f);
    split_bn<false><<<(Bz * Hc * 384 + 255) / 256, 256>>>(pA, pAct, nullptr, nullptr,
                                                          384, Bz * Hc * 384);

    // lin4: CK=512, T=384, N=6144
    conv_gemm_f16k16<1,1,true,false><<<dim3(96, 4, 1), 256>>>(
        pWH + WO4, pWL + WO4, lin4_b, pAct, pA,
        512, 384, 384, 512, 6144, 0, 0, 0);
    bn_finalize<<<1, 512>>>(bn4_g, bn4_b, 1.f / 6144.f);
    split_bn<false><<<(Bz * Hc * 384 + 255) / 256, 256>>>(pA, pAct, nullptr, nullptr,
                                                          384, Bz * Hc * 384);   // x4 split

    // lin5: reads x4 split -> raw x5
    conv_gemm_f16k16<1,1,true,false><<<dim3(96, 4, 1), 256>>>(
        pWH + WO5, pWL + WO5, lin5_b, pAct, pA,
        512, 384, 384, 512, 6144, 0, 0, 0);
    bn_finalize<<<1, 512>>>(bn5_g, bn5_b, 1.f / 6144.f);
    split_bn<true><<<(Bz * Hc * 384 + 255) / 256, 256>>>(pA, nullptr, pX5H, pX5L,
                                                         384, Bz * Hc * 384);    // x5 planes

    // pooling: M[b,i,j] = sum_t x4n[b,i,t]*x5n[b,j,t]; writes PACKED split M
    conv_gemm_f16k16<1,1,false,true><<<dim3(8, 4, 16), 256>>>(
        pX5H, pX5L, pZero, pAct, pMf,
        384, 1, 1, 384, 512, Hc * T3c, Hc * T3c, Kbot);

    // bottleneck: tensor-core fp16x3, W streamed once (DRAM-bound)
    zero_h<<<16, 512>>>();
    bottleneck_tc<<<dim3(8, 64), 256>>>(bot_w);

    bn2d_relu<<<1, 512>>>(bot_b, bnb_g, bnb_b);
    emb_kernel<<<16, 512>>>(pHn, emb_w, emb_b, pEmb);
    norm_kernel<<<16, 512>>>(pEmb, out);
}

// round 12
// speedup vs baseline: 1.1956x; 1.0826x over previous
#include <cuda_runtime.h>
#include <cuda_fp16.h>
#include <math.h>
#include <stdint.h>

// ---------------- problem constants ----------------
#define Bz   16
#define T0   400
#define F0c  40
#define Hc   512
#define T1c  396
#define T3c  384
#define Kbot (Hc*Hc)   // 262144

// weight arena offsets (elements)
#define WO1 0
#define WO2 102400        // 512*200
#define WO3 888832        // +512*1536
#define WO4 1675264       // +512*1536
#define WO5 1937408       // +512*512
#define WTOT 2199552      // +512*512

// ---------------- scratch (device globals; no allocs allowed) ----------------
__device__ float g_bufA[Bz*Hc*T1c];          // raw fp32 GEMM outputs
__device__ uint32_t g_act[Bz*Hc*T1c];        // interleaved (lo<<16|hi) split activations
__device__ __half g_wH[WTOT];
__device__ __half g_wL[WTOT];
__device__ __half g_x5H[Bz*Hc*T3c];
__device__ __half g_x5L[Bz*Hc*T3c];
__device__ uint32_t g_M[Bz*Kbot];            // pooled matrices, packed (lo16|hi16)
__device__ float g_sum[Hc];
__device__ float g_sumsq[Hc];
__device__ float g_scale[Hc];
__device__ float g_shift[Hc];
__device__ float g_h[Bz*Hc];
__device__ float g_hn[Bz*Hc];
__device__ float g_emb[Bz*Hc];
__device__ float g_zero[Hc];

// ---------------- helpers ----------------
__device__ __forceinline__ float relu20(float v)
{
    return fminf(fmaxf(v, 0.f), 20.f);
}

__device__ __forceinline__ uint32_t f16_split_pack(float v)
{
    __half h = __float2half_rn(v);
    __half l = __float2half_rn(v - __half2float(h));
    return ((uint32_t)__half_as_ushort(l) << 16) | (uint32_t)__half_as_ushort(h);
}

__device__ __forceinline__ void f16_split2(float x0, float x1, uint32_t& hw, uint32_t& lw)
{
    __half2 h = __floats2half2_rn(x0, x1);
    float2 hf = __half22float2(h);
    __half2 l = __floats2half2_rn(x0 - hf.x, x1 - hf.y);
    hw = *(uint32_t*)&h;
    lw = *(uint32_t*)&l;
}

__device__ __forceinline__ void mma_f16_k16(float* d, const uint32_t* a, const uint32_t* b)
{
    asm volatile(
        "mma.sync.aligned.m16n8k16.row.col.f32.f16.f16.f32 "
        "{%0,%1,%2,%3}, {%4,%5,%6,%7}, {%8,%9}, {%0,%1,%2,%3};"
        : "+f"(d[0]), "+f"(d[1]), "+f"(d[2]), "+f"(d[3])
        : "r"(a[0]), "r"(a[1]), "r"(a[2]), "r"(a[3]), "r"(b[0]), "r"(b[1]));
}

__device__ __forceinline__ void ldsm_x4(uint32_t* r, uint32_t saddr)
{
    asm volatile("ldmatrix.sync.aligned.m8n8.x4.shared.b16 {%0,%1,%2,%3}, [%4];"
        : "=r"(r[0]), "=r"(r[1]), "=r"(r[2]), "=r"(r[3]) : "r"(saddr));
}

__device__ __forceinline__ void sts_v2(uint32_t saddr, uint32_t v0, uint32_t v1)
{
    asm volatile("st.shared.v2.u32 [%0], {%1,%2};" :: "r"(saddr), "r"(v0), "r"(v1));
}

__device__ __forceinline__ void cp_async16(uint32_t saddr, const void* gaddr)
{
    asm volatile("cp.async.cg.shared.global [%0], [%1], 16;"
        :: "r"(saddr), "l"(gaddr));
}
#define CP_COMMIT() asm volatile("cp.async.commit_group;")
#define CP_WAIT1()  asm volatile("cp.async.wait_group 1;")

// ---------------- transpose + split ----------------
__global__ void transpose_split(const float* __restrict__ in, uint32_t* __restrict__ out)
{
    int idx = blockIdx.x * blockDim.x + threadIdx.x;
    if (idx >= Bz * T0 * F0c) return;
    int c = idx % F0c;
    int t = (idx / F0c) % T0;
    int b = idx / (F0c * T0);
    out[(b * F0c + c) * T0 + t] = f16_split_pack(in[idx]);
}

// ---------------- weight split ----------------
__global__ void split_weights(const float* __restrict__ w1, const float* __restrict__ w2,
                              const float* __restrict__ w3, const float* __restrict__ w4,
                              const float* __restrict__ w5)
{
    int i = blockIdx.x * blockDim.x + threadIdx.x;
    if (i >= WTOT) return;
    float v;
    if (i < WO2)      v = w1[i];
    else if (i < WO3) v = w2[i - WO2];
    else if (i < WO4) v = w3[i - WO3];
    else if (i < WO5) v = w4[i - WO4];
    else              v = w5[i - WO5];
    __half h = __float2half_rn(v);
    g_wH[i] = h;
    g_wL[i] = __float2half_rn(v - __half2float(h));
}

// ---------------- BN apply + clamp + split ----------------
template<bool SEP>
__global__ void split_bn(const float* __restrict__ Y, uint32_t* __restrict__ dst,
                         __half* __restrict__ dH, __half* __restrict__ dL,
                         int T, int total)
{
    int idx = blockIdx.x * blockDim.x + threadIdx.x;
    if (idx >= total) return;
    int c = (idx / T) & (Hc - 1);
    float v = relu20(g_scale[c] * Y[idx] + g_shift[c]);
    __half h = __float2half_rn(v);
    __half l = __float2half_rn(v - __half2float(h));
    if (SEP) {
        dH[idx] = h;
        dL[idx] = l;
    } else {
        dst[idx] = ((uint32_t)__half_as_ushort(l) << 16) | (uint32_t)__half_as_ushort(h);
    }
}

// ---------------- FP16x3 conv-as-GEMM: cp.async A (3-stage) + distance-2 B prefetch ----------
// A: fp16 hi/lo planes via cp.async into 3-stage smem (wait_group 1 => >=1.5 iter coverage).
// B: packed activations gathered via LDG at prefetch distance 2 (two register sets),
//    PRMT-deinterleaved, staged into 2-stage smem one iteration ahead of use.
// BM=128 BN=64 BK=16, 256 thr, warps 4x2, warp tile 32x32; RSTR=12 -> LDSM conflict-free.
#define RSTR 12
#define ASTG_B (128 * RSTR * 4)   // bytes per A stage per plane
#define BSTG_B (64 * RSTR * 4)    // bytes per B stage per plane
template<int KW, int DIL, bool STATS, bool PACK>
__global__ __launch_bounds__(256, 3)
void conv_gemm_f16k16(const __half* __restrict__ AH, const __half* __restrict__ AL,
                      const float* __restrict__ bias,
                      const uint32_t* __restrict__ X, float* __restrict__ Y,
                      int C, int Tin, int Tout, int CK, int Ntot,
                      int strideA, int strideX, int strideY)
{
    AH += (size_t)blockIdx.z * strideA;
    AL += (size_t)blockIdx.z * strideA;
    X  += (size_t)blockIdx.z * strideX;
    Y  += (size_t)blockIdx.z * strideY;

    __shared__ uint32_t AsH[3][128][RSTR];
    __shared__ uint32_t AsL[3][128][RSTR];
    __shared__ uint32_t BsH[2][64][RSTR];
    __shared__ uint32_t BsL[2][64][RSTR];

    const int tid  = threadIdx.x;
    const int lane = tid & 31;
    const int warp = tid >> 5;
    const int wm = warp >> 1;      // 0..3 (32 rows each)
    const int wn = warp & 1;       // 0..1 (32 cols each)
    const int oBase = blockIdx.y * 128;
    const int nBase = blockIdx.x * 64;

    float acc[2][4][4];
    #pragma unroll
    for (int i = 0; i < 2; i++)
        #pragma unroll
        for (int j = 0; j < 4; j++)
            #pragma unroll
            for (int r = 0; r < 4; r++) acc[i][j][r] = 0.f;

    // A loader: row = tid>>1; 8 halfs (16B) at half-col (tid&1)*8
    const int aRow = tid >> 1;
    const int aC0  = (tid & 1) * 8;
    // B loader: n = tid&63, k elements bG*4..+3
    const int bN  = tid & 63;
    const int bG  = tid >> 6;

    const int nIdx = nBase + bN;
    const bool nValid = (nIdx < Ntot);
    int nb = 0, nt0 = 0;
    if (nValid) { nb = nIdx / Tout; nt0 = nIdx - nb * Tout; }
    const uint32_t* Xbase = X + ((size_t)nb * C) * Tin + nt0;
    const __half* ArowH = AH + (size_t)(oBase + aRow) * CK + aC0;
    const __half* ArowL = AL + (size_t)(oBase + aRow) * CK + aC0;

    const uint32_t baseAH = (uint32_t)__cvta_generic_to_shared(&AsH[0][0][0]);
    const uint32_t baseAL = (uint32_t)__cvta_generic_to_shared(&AsL[0][0][0]);
    const uint32_t baseBH = (uint32_t)__cvta_generic_to_shared(&BsH[0][0][0]);
    const uint32_t baseBL = (uint32_t)__cvta_generic_to_shared(&BsL[0][0][0]);

    const uint32_t stA = (aRow * RSTR + (tid & 1) * 4) * 4;  // 16B-aligned
    const uint32_t stB = (bN * RSTR + bG * 2) * 4;

    // LDSM source offsets
    const int aFragRow = (lane & 7) + ((lane >> 3) & 1) * 8;
    const int aFragWord = (lane >> 4) * 4;
    const uint32_t ldA0 = ((wm * 32 + aFragRow) * RSTR + aFragWord) * 4;
    const int bFragRow = (lane & 7) + ((lane >> 4) << 3);
    const int bFragWord = ((lane >> 3) & 1) * 4;
    const uint32_t ldB0 = ((wn * 32 + bFragRow) * RSTR + bFragWord) * 4;

    const int nSteps = (CK + 15) >> 4;

    // B register prefetch (distance 2): pbw[k%2] holds step k's gather
    uint32_t pbw[2][4];
    #pragma unroll
    for (int set = 0; set < 2; set++) {
        int k0 = set * 16;
        #pragma unroll
        for (int p = 0; p < 4; p++) {
            int kkg = k0 + bG * 4 + p;
            uint32_t v = 0;
            if (nValid && kkg < CK && set < nSteps) {
                int c = kkg / KW;
                int kw = kkg - c * KW;
                v = Xbase[c * Tin + kw * DIL];
            }
            pbw[set][p] = v;
        }
    }

    // A cp.async prologue: stages 0 and 1 (each its own group)
    cp_async16(baseAH + stA, ArowH);
    cp_async16(baseAL + stA, ArowL);
    CP_COMMIT();
    if (1 < nSteps) {
        cp_async16(baseAH + ASTG_B + stA, ArowH + 16);
        cp_async16(baseAL + ASTG_B + stA, ArowL + 16);
    }
    CP_COMMIT();

    // stage B[0]
    {
        uint32_t h0 = __byte_perm(pbw[0][0], pbw[0][1], 0x5410);
        uint32_t h1 = __byte_perm(pbw[0][2], pbw[0][3], 0x5410);
        uint32_t l0 = __byte_perm(pbw[0][0], pbw[0][1], 0x7632);
        uint32_t l1 = __byte_perm(pbw[0][2], pbw[0][3], 0x7632);
        sts_v2(baseBH + stB, h0, h1);
        sts_v2(baseBL + stB, l0, l1);
    }
    CP_WAIT1();          // A stage 0 complete
    __syncthreads();

    for (int s = 0; s < nSteps; s++) {
        // 1. LDG B[s+2] into pbw[s&1] (long-latency, start first)
        if (s + 2 < nSteps) {
            int k0 = (s + 2) * 16;
            #pragma unroll
            for (int p = 0; p < 4; p++) {
                int kkg = k0 + bG * 4 + p;
                uint32_t v = 0;
                if (nValid && kkg < CK) {
                    int c = kkg / KW;
                    int kw = kkg - c * KW;
                    v = Xbase[c * Tin + kw * DIL];
                }
                pbw[s & 1][p] = v;
            }
        }

        // 2. STS B[s+1] from pbw[(s+1)&1]
        if (s + 1 < nSteps) {
            const uint32_t* pw = pbw[(s + 1) & 1];
            const uint32_t offB = ((s + 1) & 1) * BSTG_B;
            uint32_t h0 = __byte_perm(pw[0], pw[1], 0x5410);
            uint32_t h1 = __byte_perm(pw[2], pw[3], 0x5410);
            uint32_t l0 = __byte_perm(pw[0], pw[1], 0x7632);
            uint32_t l1 = __byte_perm(pw[2], pw[3], 0x7632);
            sts_v2(baseBH + offB + stB, h0, h1);
            sts_v2(baseBL + offB + stB, l0, l1);
        }

        // 3. cp.async A[s+2]
        if (s + 2 < nSteps) {
            int k0 = (s + 2) * 16;
            const uint32_t offA = ((s + 2) % 3) * ASTG_B;
            cp_async16(baseAH + offA + stA, ArowH + k0);
            cp_async16(baseAL + offA + stA, ArowL + k0);
        }
        CP_COMMIT();

        // 4. consume step s
        {
            const uint32_t offA = (s % 3) * ASTG_B;
            const uint32_t offB = (s & 1) * BSTG_B;
            uint32_t bHf[8], bLf[8];
            ldsm_x4(bHf,     baseBH + offB + ldB0);
            ldsm_x4(bHf + 4, baseBH + offB + ldB0 + 16 * RSTR * 4);
            ldsm_x4(bLf,     baseBL + offB + ldB0);
            ldsm_x4(bLf + 4, baseBL + offB + ldB0 + 16 * RSTR * 4);
            #pragma unroll
            for (int mt = 0; mt < 2; mt++) {
                const uint32_t mtOff = mt * 16 * RSTR * 4;
                uint32_t aHf[4], aLf[4];
                ldsm_x4(aHf, baseAH + offA + ldA0 + mtOff);
                ldsm_x4(aLf, baseAL + offA + ldA0 + mtOff);
                #pragma unroll
                for (int nt = 0; nt < 4; nt++) {
                    mma_f16_k16(acc[mt][nt], aHf, bLf + nt * 2);
                    mma_f16_k16(acc[mt][nt], aLf, bHf + nt * 2);
                    mma_f16_k16(acc[mt][nt], aHf, bHf + nt * 2);
                }
            }
        }

        // 5. ensure A[s+1] landed; publish B[s+1]
        CP_WAIT1();
        __syncthreads();
    }

    // epilogue
    #pragma unroll
    for (int mt = 0; mt < 2; mt++) {
        int row0 = oBase + wm * 32 + mt * 16 + (lane >> 2);
        float b0 = bias[row0];
        float b1 = bias[row0 + 8];
        float s0 = 0.f, q0 = 0.f, s1 = 0.f, q1 = 0.f;
        #pragma unroll
        for (int nt = 0; nt < 4; nt++) {
            int col0 = nBase + wn * 32 + nt * 8 + (lane & 3) * 2;
            #pragma unroll
            for (int cc = 0; cc < 2; cc++) {
                int col = col0 + cc;
                if (col < Ntot) {
                    float v0 = acc[mt][nt][cc]     + b0;
                    float v1 = acc[mt][nt][2 + cc] + b1;
                    int b = col / Tout;
                    int t = col - b * Tout;
                    size_t base = ((size_t)b * Hc) * Tout + t;
                    if (PACK) {
                        Y[base + (size_t)row0 * Tout]       = __uint_as_float(f16_split_pack(v0));
                        Y[base + (size_t)(row0 + 8) * Tout] = __uint_as_float(f16_split_pack(v1));
                    } else {
                        Y[base + (size_t)row0 * Tout]       = v0;
                        Y[base + (size_t)(row0 + 8) * Tout] = v1;
                    }
                    if (STATS) {
                        s0 += v0; q0 += v0 * v0;
                        s1 += v1; q1 += v1 * v1;
                    }
                }
            }
        }
        if (STATS) {
            #pragma unroll
            for (int off = 2; off >= 1; off >>= 1) {
                s0 += __shfl_down_sync(0xffffffffu, s0, off);
                q0 += __shfl_down_sync(0xffffffffu, q0, off);
                s1 += __shfl_down_sync(0xffffffffu, s1, off);
                q1 += __shfl_down_sync(0xffffffffu, q1, off);
            }
            if ((lane & 3) == 0) {
                atomicAdd(&g_sum[row0], s0);
                atomicAdd(&g_sumsq[row0], q0);
                atomicAdd(&g_sum[row0 + 8], s1);
                atomicAdd(&g_sumsq[row0 + 8], q1);
            }
        }
    }
}

// ---------------- BN finalize ----------------
__global__ void bn_finalize(const float* __restrict__ g, const float* __restrict__ be,
                            float invN)
{
    int c = threadIdx.x;   // 512
    float s = g_sum[c], q = g_sumsq[c];
    float m = s * invN;
    float var = q * invN - m * m;
    float a = g[c] * rsqrtf(var + 1e-5f);
    g_scale[c] = a;
    g_shift[c] = be[c] - a * m;
    g_sum[c] = 0.f;
    g_sumsq[c] = 0.f;
}

// ---------------- bottleneck (tensor-core, fp16x3) ----------------
__global__ void zero_h()
{
    g_h[blockIdx.x * blockDim.x + threadIdx.x] = 0.f;
}

__global__ __launch_bounds__(256)
void bottleneck_tc(const float* __restrict__ W)
{
    const int lane = threadIdx.x & 31;
    const int warp = threadIdx.x >> 5;
    const int o0 = blockIdx.x * 64 + warp * 8;
    const int kb = blockIdx.y * 4096;

    const int r  = lane >> 2;
    const int kq = (lane & 3) * 2;

    const uint32_t* m0 = g_M + (size_t)r * Kbot + kb + kq;
    const uint32_t* m1 = g_M + (size_t)(r + 8) * Kbot + kb + kq;
    const float*    w0 = W + (size_t)(o0 + r) * Kbot + kb + kq;

    float acc[4] = {0.f, 0.f, 0.f, 0.f};

    #pragma unroll 2
    for (int s = 0; s < 4096; s += 16) {
        uint2 u0 = *(const uint2*)(m0 + s);
        uint2 u2 = *(const uint2*)(m0 + s + 8);
        uint2 u1 = *(const uint2*)(m1 + s);
        uint2 u3 = *(const uint2*)(m1 + s + 8);
        float2 wv0 = *(const float2*)(w0 + s);
        float2 wv1 = *(const float2*)(w0 + s + 8);

        uint32_t aH[4], aL[4];
        aH[0] = __byte_perm(u0.x, u0.y, 0x5410);  aL[0] = __byte_perm(u0.x, u0.y, 0x7632);
        aH[1] = __byte_perm(u1.x, u1.y, 0x5410);  aL[1] = __byte_perm(u1.x, u1.y, 0x7632);
        aH[2] = __byte_perm(u2.x, u2.y, 0x5410);  aL[2] = __byte_perm(u2.x, u2.y, 0x7632);
        aH[3] = __byte_perm(u3.x, u3.y, 0x5410);  aL[3] = __byte_perm(u3.x, u3.y, 0x7632);

        uint32_t bH[2], bL[2];
        f16_split2(wv0.x, wv0.y, bH[0], bL[0]);
        f16_split2(wv1.x, wv1.y, bH[1], bL[1]);

        mma_f16_k16(acc, aH, bL);
        mma_f16_k16(acc, aL, bH);
        mma_f16_k16(acc, aH, bH);
    }

    int o = o0 + kq;
    atomicAdd(&g_h[r * Hc + o],           acc[0]);
    atomicAdd(&g_h[r * Hc + o + 1],       acc[1]);
    atomicAdd(&g_h[(r + 8) * Hc + o],     acc[2]);
    atomicAdd(&g_h[(r + 8) * Hc + o + 1], acc[3]);
}

// ---------------- BN over batch + relu20 ----------------
__global__ void bn2d_relu(const float* __restrict__ bot_b, const float* __restrict__ gg,
                          const float* __restrict__ gb)
{
    int o = threadIdx.x;
    float v[16];
    float s = 0.f, sq = 0.f;
    #pragma unroll
    for (int b = 0; b < 16; b++) {
        float x = g_h[b * Hc + o] + bot_b[o];
        v[b] = x; s += x; sq += x * x;
    }
    float m = s * (1.f / 16.f);
    float var = sq * (1.f / 16.f) - m * m;
    float a = gg[o] * rsqrtf(var + 1e-5f);
    float d = gb[o] - a * m;
    #pragma unroll
    for (int b = 0; b < 16; b++) {
        float z = a * v[b] + d;
        g_hn[b * Hc + o] = fminf(fmaxf(z, 0.f), 20.f);
    }
}

// ---------------- embedding GEMV + bias ----------------
__global__ void emb_kernel(const float* __restrict__ h, const float* __restrict__ W,
                           const float* __restrict__ bias, float* __restrict__ emb)
{
    int b = blockIdx.x;
    int warp = threadIdx.x >> 5, lane = threadIdx.x & 31;
    __shared__ float hs[512];
    hs[threadIdx.x] = h[b * Hc + threadIdx.x];
    __syncthreads();
    for (int e = warp; e < 512; e += 16) {
        float s = 0.f;
        for (int c = lane; c < 512; c += 32)
            s += hs[c] * W[e * 512 + c];
        #pragma unroll
        for (int off = 16; off; off >>= 1)
            s += __shfl_down_sync(0xffffffffu, s, off);
        if (lane == 0) emb[b * Hc + e] = s + bias[e];
    }
}

// ---------------- L2 normalize * 10 ----------------
__global__ void norm_kernel(const float* __restrict__ emb, float* __restrict__ out)
{
    int b = blockIdx.x;
    int t = threadIdx.x;
    __shared__ float red[512];
    float v = emb[b * 512 + t];
    red[t] = v * v;
    __syncthreads();
    for (int s = 256; s > 0; s >>= 1) {
        if (t < s) red[t] += red[t + s];
        __syncthreads();
    }
    float scale = 10.f / sqrtf(red[0] + 1e-10f);
    out[b * 512 + t] = v * scale;
}

// ---------------- launcher ----------------
extern "C" void kernel_launch(void* const* d_in, const int* in_sizes, int n_in,
                              void* d_out, int out_size)
{
    const float* input_x = (const float*)d_in[0];
    const float* conv1_w = (const float*)d_in[1];
    const float* conv1_b = (const float*)d_in[2];
    const float* bn1_g   = (const float*)d_in[3];
    const float* bn1_b   = (const float*)d_in[4];
    const float* conv2_w = (const float*)d_in[5];
    const float* conv2_b = (const float*)d_in[6];
    const float* bn2_g   = (const float*)d_in[7];
    const float* bn2_b   = (const float*)d_in[8];
    const float* conv3_w = (const float*)d_in[9];
    const float* conv3_b = (const float*)d_in[10];
    const float* bn3_g   = (const float*)d_in[11];
    const float* bn3_b   = (const float*)d_in[12];
    const float* lin4_w  = (const float*)d_in[13];
    const float* lin4_b  = (const float*)d_in[14];
    const float* bn4_g   = (const float*)d_in[15];
    const float* bn4_b   = (const float*)d_in[16];
    const float* lin5_w  = (const float*)d_in[17];
    const float* lin5_b  = (const float*)d_in[18];
    const float* bn5_g   = (const float*)d_in[19];
    const float* bn5_b   = (const float*)d_in[20];
    const float* bot_w   = (const float*)d_in[21];
    const float* bot_b   = (const float*)d_in[22];
    const float* bnb_g   = (const float*)d_in[23];
    const float* bnb_b   = (const float*)d_in[24];
    const float* emb_w   = (const float*)d_in[25];
    const float* emb_b   = (const float*)d_in[26];
    float* out = (float*)d_out;

    float *pA, *pZero, *pHn, *pEmb, *pMf;
    uint32_t *pAct;
    __half *pWH, *pWL, *pX5H, *pX5L;
    cudaGetSymbolAddress((void**)&pA,   g_bufA);
    cudaGetSymbolAddress((void**)&pAct, g_act);
    cudaGetSymbolAddress((void**)&pWH,  g_wH);
    cudaGetSymbolAddress((void**)&pWL,  g_wL);
    cudaGetSymbolAddress((void**)&pX5H, g_x5H);
    cudaGetSymbolAddress((void**)&pX5L, g_x5L);
    cudaGetSymbolAddress((void**)&pMf,  g_M);
    cudaGetSymbolAddress((void**)&pZero,g_zero);
    cudaGetSymbolAddress((void**)&pHn,  g_hn);
    cudaGetSymbolAddress((void**)&pEmb, g_emb);

    // upfront: weight split + input transpose/split
    split_weights<<<(WTOT + 255) / 256, 256>>>(conv1_w, conv2_w, conv3_w, lin4_w, lin5_w);
    transpose_split<<<(Bz * T0 * F0c + 255) / 256, 256>>>(input_x, pAct);

    // conv1: CK=200, T 400->396, N=6336
    conv_gemm_f16k16<5,1,true,false><<<dim3(99, 4, 1), 256>>>(
        pWH + WO1, pWL + WO1, conv1_b, pAct, pA,
        40, 400, 396, 200, 6336, 0, 0, 0);
    bn_finalize<<<1, 512>>>(bn1_g, bn1_b, 1.f / 6336.f);
    split_bn<false><<<(Bz * Hc * 396 + 255) / 256, 256>>>(pA, pAct, nullptr, nullptr,
                                                          396, Bz * Hc * 396);

    // conv2: CK=1536, T 396->392, N=6272
    conv_gemm_f16k16<3,2,true,false><<<dim3(98, 4, 1), 256>>>(
        pWH + WO2, pWL + WO2, conv2_b, pAct, pA,
        512, 396, 392, 1536, 6272, 0, 0, 0);
    bn_finalize<<<1, 512>>>(bn2_g, bn2_b, 1.f / 6272.f);
    split_bn<false><<<(Bz * Hc * 392 + 255) / 256, 256>>>(pA, pAct, nullptr, nullptr,
                                                          392, Bz * Hc * 392);

    // conv3: CK=1536, T 392->384, N=6144
    conv_gemm_f16k16<3,4,true,false><<<dim3(96, 4, 1), 256>>>(
        pWH + WO3, pWL + WO3, conv3_b, pAct, pA,
        512, 392, 384, 1536, 6144, 0, 0, 0);
    bn_finalize<<<1, 512>>>(bn3_g, bn3_b, 1.f / 6144.f);
    split_bn<false><<<(Bz * Hc * 384 + 255) / 256, 256>>>(pA, pAct, nullptr, nullptr,
                                                          384, Bz * Hc * 384);

    // lin4: CK=512, T=384, N=6144
    conv_gemm_f16k16<1,1,true,false><<<dim3(96, 4, 1), 256>>>(
        pWH + WO4, pWL + WO4, lin4_b, pAct, pA,
        512, 384, 384, 512, 6144, 0, 0, 0);
    bn_finalize<<<1, 512>>>(bn4_g, bn4_b, 1.f / 6144.f);
    split_bn<false><<<(Bz * Hc * 384 + 255) / 256, 256>>>(pA, pAct, nullptr, nullptr,
                                                          384, Bz * Hc * 384);   // x4 split

    // lin5: reads x4 split -> raw x5
    conv_gemm_f16k16<1,1,true,false><<<dim3(96, 4, 1), 256>>>(
        pWH + WO5, pWL + WO5, lin5_b, pAct, pA,
        512, 384, 384, 512, 6144, 0, 0, 0);
    bn_finalize<<<1, 512>>>(bn5_g, bn5_b, 1.f / 6144.f);
    split_bn<true><<<(Bz * Hc * 384 + 255) / 256, 256>>>(pA, nullptr, pX5H, pX5L,
                                                         384, Bz * Hc * 384);    // x5 planes

    // pooling: writes PACKED split M
    conv_gemm_f16k16<1,1,false,true><<<dim3(8, 4, 16), 256>>>(
        pX5H, pX5L, pZero, pAct, pMf,
        384, 1, 1, 384, 512, Hc * T3c, Hc * T3c, Kbot);

    // bottleneck: tensor-core fp16x3, W streamed once
    zero_h<<<16, 512>>>();
    bottleneck_tc<<<dim3(8, 64), 256>>>(bot_w);

    bn2d_relu<<<1, 512>>>(bot_b, bnb_g, bnb_b);
    emb_kernel<<<16, 512>>>(pHn, emb_w, emb_b, pEmb);
    norm_kernel<<<16, 512>>>(pEmb, out);
}

// round 13
// speedup vs baseline: 1.1992x; 1.0030x over previous
#include <cuda_runtime.h>
#include <cuda_fp16.h>
#include <math.h>
#include <stdint.h>

// ---------------- problem constants ----------------
#define Bz   16
#define T0   400
#define F0c  40
#define Hc   512
#define T1c  396
#define T3c  384
#define Kbot (Hc*Hc)   // 262144

// weight arena offsets (elements)
#define WO1 0
#define WO2 102400        // 512*200
#define WO3 888832        // +512*1536
#define WO4 1675264       // +512*1536
#define WO5 1937408       // +512*512
#define WTOT 2199552      // +512*512

// ---------------- scratch (device globals; no allocs allowed) ----------------
__device__ float g_bufA[Bz*Hc*T1c];          // raw fp32 GEMM outputs
__device__ uint32_t g_act[Bz*Hc*T1c];        // interleaved (lo<<16|hi) split activations
__device__ __half g_wH[WTOT];
__device__ __half g_wL[WTOT];
__device__ __half g_x5H[Bz*Hc*T3c];
__device__ __half g_x5L[Bz*Hc*T3c];
__device__ uint32_t g_M[Bz*Kbot];            // pooled matrices, packed (lo16|hi16)
__device__ float g_sums[5][Hc];              // per-layer BN stat accumulators
__device__ float g_sumsqs[5][Hc];
__device__ float g_h[Bz*Hc];
__device__ float g_zero[Hc];                 // stays zero

// ---------------- helpers ----------------
__device__ __forceinline__ float relu20(float v)
{
    return fminf(fmaxf(v, 0.f), 20.f);
}

__device__ __forceinline__ uint32_t f16_split_pack(float v)
{
    __half h = __float2half_rn(v);
    __half l = __float2half_rn(v - __half2float(h));
    return ((uint32_t)__half_as_ushort(l) << 16) | (uint32_t)__half_as_ushort(h);
}

__device__ __forceinline__ void f16_split2(float x0, float x1, uint32_t& hw, uint32_t& lw)
{
    __half2 h = __floats2half2_rn(x0, x1);
    float2 hf = __half22float2(h);
    __half2 l = __floats2half2_rn(x0 - hf.x, x1 - hf.y);
    hw = *(uint32_t*)&h;
    lw = *(uint32_t*)&l;
}

__device__ __forceinline__ void mma_f16_k16(float* d, const uint32_t* a, const uint32_t* b)
{
    asm volatile(
        "mma.sync.aligned.m16n8k16.row.col.f32.f16.f16.f32 "
        "{%0,%1,%2,%3}, {%4,%5,%6,%7}, {%8,%9}, {%0,%1,%2,%3};"
        : "+f"(d[0]), "+f"(d[1]), "+f"(d[2]), "+f"(d[3])
        : "r"(a[0]), "r"(a[1]), "r"(a[2]), "r"(a[3]), "r"(b[0]), "r"(b[1]));
}

__device__ __forceinline__ void ldsm_x4(uint32_t* r, uint32_t saddr)
{
    asm volatile("ldmatrix.sync.aligned.m8n8.x4.shared.b16 {%0,%1,%2,%3}, [%4];"
        : "=r"(r[0]), "=r"(r[1]), "=r"(r[2]), "=r"(r[3]) : "r"(saddr));
}

__device__ __forceinline__ void sts_v2(uint32_t saddr, uint32_t v0, uint32_t v1)
{
    asm volatile("st.shared.v2.u32 [%0], {%1,%2};" :: "r"(saddr), "r"(v0), "r"(v1));
}

__device__ __forceinline__ void cp_async16(uint32_t saddr, const void* gaddr)
{
    asm volatile("cp.async.cg.shared.global [%0], [%1], 16;"
        :: "r"(saddr), "l"(gaddr));
}
#define CP_COMMIT() asm volatile("cp.async.commit_group;")
#define CP_WAIT1()  asm volatile("cp.async.wait_group 1;")

// ---------------- prep: weight split + input transpose/split + replay zeroing ----------
__global__ void prep(const float* __restrict__ in,
                     const float* __restrict__ w1, const float* __restrict__ w2,
                     const float* __restrict__ w3, const float* __restrict__ w4,
                     const float* __restrict__ w5, uint32_t* __restrict__ act)
{
    int i = blockIdx.x * blockDim.x + threadIdx.x;
    if (i < WTOT) {
        float v;
        if (i < WO2)      v = w1[i];
        else if (i < WO3) v = w2[i - WO2];
        else if (i < WO4) v = w3[i - WO3];
        else if (i < WO5) v = w4[i - WO4];
        else              v = w5[i - WO5];
        __half h = __float2half_rn(v);
        g_wH[i] = h;
        g_wL[i] = __float2half_rn(v - __half2float(h));
    }
    if (i < Bz * T0 * F0c) {
        int c = i % F0c;
        int t = (i / F0c) % T0;
        int b = i / (F0c * T0);
        act[(b * F0c + c) * T0 + t] = f16_split_pack(in[i]);
    }
    if (i < 5 * Hc) {
        (&g_sums[0][0])[i] = 0.f;
        (&g_sumsqs[0][0])[i] = 0.f;
    }
    if (i < Bz * Hc) {
        g_h[i] = 0.f;
    }
}

// ---------------- BN finalize+apply+clamp+split (fused) ----------------
// Computes per-channel scale/shift from the layer's sum arrays in smem, then
// grid-strides over elements. SEP: write separate hi/lo planes (for x5).
template<bool SEP>
__global__ __launch_bounds__(512)
void split_bn(const float* __restrict__ Y, uint32_t* __restrict__ dst,
              __half* __restrict__ dH, __half* __restrict__ dL,
              const float* __restrict__ sums, const float* __restrict__ sumsqs,
              const float* __restrict__ gamma, const float* __restrict__ beta,
              float invN, int T, int total)
{
    __shared__ float sSc[Hc];
    __shared__ float sSh[Hc];
    {
        int c = threadIdx.x;
        float s = sums[c], q = sumsqs[c];
        float m = s * invN;
        float var = q * invN - m * m;
        float a = gamma[c] * rsqrtf(var + 1e-5f);
        sSc[c] = a;
        sSh[c] = beta[c] - a * m;
    }
    __syncthreads();
    for (int idx = blockIdx.x * 512 + threadIdx.x; idx < total; idx += gridDim.x * 512) {
        int c = (idx / T) & (Hc - 1);
        float v = relu20(sSc[c] * Y[idx] + sSh[c]);
        __half h = __float2half_rn(v);
        __half l = __float2half_rn(v - __half2float(h));
        if (SEP) {
            dH[idx] = h;
            dL[idx] = l;
        } else {
            dst[idx] = ((uint32_t)__half_as_ushort(l) << 16) | (uint32_t)__half_as_ushort(h);
        }
    }
}

// ---------------- FP16x3 conv-as-GEMM: cp.async A (3-stage) + distance-2 B prefetch ----------
#define RSTR 12
#define ASTG_B (128 * RSTR * 4)
#define BSTG_B (64 * RSTR * 4)
template<int KW, int DIL, bool STATS, bool PACK>
__global__ __launch_bounds__(256, 3)
void conv_gemm_f16k16(const __half* __restrict__ AH, const __half* __restrict__ AL,
                      const float* __restrict__ bias,
                      const uint32_t* __restrict__ X, float* __restrict__ Y,
                      float* __restrict__ oSum, float* __restrict__ oSumsq,
                      int C, int Tin, int Tout, int CK, int Ntot,
                      int strideA, int strideX, int strideY)
{
    AH += (size_t)blockIdx.z * strideA;
    AL += (size_t)blockIdx.z * strideA;
    X  += (size_t)blockIdx.z * strideX;
    Y  += (size_t)blockIdx.z * strideY;

    __shared__ uint32_t AsH[3][128][RSTR];
    __shared__ uint32_t AsL[3][128][RSTR];
    __shared__ uint32_t BsH[2][64][RSTR];
    __shared__ uint32_t BsL[2][64][RSTR];

    const int tid  = threadIdx.x;
    const int lane = tid & 31;
    const int warp = tid >> 5;
    const int wm = warp >> 1;
    const int wn = warp & 1;
    const int oBase = blockIdx.y * 128;
    const int nBase = blockIdx.x * 64;

    float acc[2][4][4];
    #pragma unroll
    for (int i = 0; i < 2; i++)
        #pragma unroll
        for (int j = 0; j < 4; j++)
            #pragma unroll
            for (int r = 0; r < 4; r++) acc[i][j][r] = 0.f;

    const int aRow = tid >> 1;
    const int bN  = tid & 63;
    const int bG  = tid >> 6;

    const int nIdx = nBase + bN;
    const bool nValid = (nIdx < Ntot);
    int nb = 0, nt0 = 0;
    if (nValid) { nb = nIdx / Tout; nt0 = nIdx - nb * Tout; }
    const uint32_t* Xbase = X + ((size_t)nb * C) * Tin + nt0;
    const __half* ArowH = AH + (size_t)(oBase + aRow) * CK + (tid & 1) * 8;
    const __half* ArowL = AL + (size_t)(oBase + aRow) * CK + (tid & 1) * 8;

    const uint32_t baseAH = (uint32_t)__cvta_generic_to_shared(&AsH[0][0][0]);
    const uint32_t baseAL = (uint32_t)__cvta_generic_to_shared(&AsL[0][0][0]);
    const uint32_t baseBH = (uint32_t)__cvta_generic_to_shared(&BsH[0][0][0]);
    const uint32_t baseBL = (uint32_t)__cvta_generic_to_shared(&BsL[0][0][0]);

    const uint32_t stA = (aRow * RSTR + (tid & 1) * 4) * 4;
    const uint32_t stB = (bN * RSTR + bG * 2) * 4;

    const int aFragRow = (lane & 7) + ((lane >> 3) & 1) * 8;
    const int aFragWord = (lane >> 4) * 4;
    const uint32_t ldA0 = ((wm * 32 + aFragRow) * RSTR + aFragWord) * 4;
    const int bFragRow = (lane & 7) + ((lane >> 4) << 3);
    const int bFragWord = ((lane >> 3) & 1) * 4;
    const uint32_t ldB0 = ((wn * 32 + bFragRow) * RSTR + bFragWord) * 4;

    const int nSteps = (CK + 15) >> 4;

    uint32_t pbw[2][4];
    #pragma unroll
    for (int set = 0; set < 2; set++) {
        int k0 = set * 16;
        #pragma unroll
        for (int p = 0; p < 4; p++) {
            int kkg = k0 + bG * 4 + p;
            uint32_t v = 0;
            if (nValid && kkg < CK && set < nSteps) {
                int c = kkg / KW;
                int kw = kkg - c * KW;
                v = Xbase[c * Tin + kw * DIL];
            }
            pbw[set][p] = v;
        }
    }

    cp_async16(baseAH + stA, ArowH);
    cp_async16(baseAL + stA, ArowL);
    CP_COMMIT();
    if (1 < nSteps) {
        cp_async16(baseAH + ASTG_B + stA, ArowH + 16);
        cp_async16(baseAL + ASTG_B + stA, ArowL + 16);
    }
    CP_COMMIT();

    {
        uint32_t h0 = __byte_perm(pbw[0][0], pbw[0][1], 0x5410);
        uint32_t h1 = __byte_perm(pbw[0][2], pbw[0][3], 0x5410);
        uint32_t l0 = __byte_perm(pbw[0][0], pbw[0][1], 0x7632);
        uint32_t l1 = __byte_perm(pbw[0][2], pbw[0][3], 0x7632);
        sts_v2(baseBH + stB, h0, h1);
        sts_v2(baseBL + stB, l0, l1);
    }
    CP_WAIT1();
    __syncthreads();

    for (int s = 0; s < nSteps; s++) {
        if (s + 2 < nSteps) {
            int k0 = (s + 2) * 16;
            #pragma unroll
            for (int p = 0; p < 4; p++) {
                int kkg = k0 + bG * 4 + p;
                uint32_t v = 0;
                if (nValid && kkg < CK) {
                    int c = kkg / KW;
                    int kw = kkg - c * KW;
                    v = Xbase[c * Tin + kw * DIL];
                }
                pbw[s & 1][p] = v;
            }
        }

        if (s + 1 < nSteps) {
            const uint32_t* pw = pbw[(s + 1) & 1];
            const uint32_t offB = ((s + 1) & 1) * BSTG_B;
            uint32_t h0 = __byte_perm(pw[0], pw[1], 0x5410);
            uint32_t h1 = __byte_perm(pw[2], pw[3], 0x5410);
            uint32_t l0 = __byte_perm(pw[0], pw[1], 0x7632);
            uint32_t l1 = __byte_perm(pw[2], pw[3], 0x7632);
            sts_v2(baseBH + offB + stB, h0, h1);
            sts_v2(baseBL + offB + stB, l0, l1);
        }

        if (s + 2 < nSteps) {
            int k0 = (s + 2) * 16;
            const uint32_t offA = ((s + 2) % 3) * ASTG_B;
            cp_async16(baseAH + offA + stA, ArowH + k0);
            cp_async16(baseAL + offA + stA, ArowL + k0);
        }
        CP_COMMIT();

        {
            const uint32_t offA = (s % 3) * ASTG_B;
            const uint32_t offB = (s & 1) * BSTG_B;
            uint32_t bHf[8], bLf[8];
            ldsm_x4(bHf,     baseBH + offB + ldB0);
            ldsm_x4(bHf + 4, baseBH + offB + ldB0 + 16 * RSTR * 4);
            ldsm_x4(bLf,     baseBL + offB + ldB0);
            ldsm_x4(bLf + 4, baseBL + offB + ldB0 + 16 * RSTR * 4);
            #pragma unroll
            for (int mt = 0; mt < 2; mt++) {
                const uint32_t mtOff = mt * 16 * RSTR * 4;
                uint32_t aHf[4], aLf[4];
                ldsm_x4(aHf, baseAH + offA + ldA0 + mtOff);
                ldsm_x4(aLf, baseAL + offA + ldA0 + mtOff);
                #pragma unroll
                for (int nt = 0; nt < 4; nt++) {
                    mma_f16_k16(acc[mt][nt], aHf, bLf + nt * 2);
                    mma_f16_k16(acc[mt][nt], aLf, bHf + nt * 2);
                    mma_f16_k16(acc[mt][nt], aHf, bHf + nt * 2);
                }
            }
        }

        CP_WAIT1();
        __syncthreads();
    }

    // epilogue
    #pragma unroll
    for (int mt = 0; mt < 2; mt++) {
        int row0 = oBase + wm * 32 + mt * 16 + (lane >> 2);
        float b0 = bias[row0];
        float b1 = bias[row0 + 8];
        float s0 = 0.f, q0 = 0.f, s1 = 0.f, q1 = 0.f;
        #pragma unroll
        for (int nt = 0; nt < 4; nt++) {
            int col0 = nBase + wn * 32 + nt * 8 + (lane & 3) * 2;
            #pragma unroll
            for (int cc = 0; cc < 2; cc++) {
                int col = col0 + cc;
                if (col < Ntot) {
                    float v0 = acc[mt][nt][cc]     + b0;
                    float v1 = acc[mt][nt][2 + cc] + b1;
                    int b = col / Tout;
                    int t = col - b * Tout;
                    size_t base = ((size_t)b * Hc) * Tout + t;
                    if (PACK) {
                        Y[base + (size_t)row0 * Tout]       = __uint_as_float(f16_split_pack(v0));
                        Y[base + (size_t)(row0 + 8) * Tout] = __uint_as_float(f16_split_pack(v1));
                    } else {
                        Y[base + (size_t)row0 * Tout]       = v0;
                        Y[base + (size_t)(row0 + 8) * Tout] = v1;
                    }
                    if (STATS) {
                        s0 += v0; q0 += v0 * v0;
                        s1 += v1; q1 += v1 * v1;
                    }
                }
            }
        }
        if (STATS) {
            #pragma unroll
            for (int off = 2; off >= 1; off >>= 1) {
                s0 += __shfl_down_sync(0xffffffffu, s0, off);
                q0 += __shfl_down_sync(0xffffffffu, q0, off);
                s1 += __shfl_down_sync(0xffffffffu, s1, off);
                q1 += __shfl_down_sync(0xffffffffu, q1, off);
            }
            if ((lane & 3) == 0) {
                atomicAdd(&oSum[row0], s0);
                atomicAdd(&oSumsq[row0], q0);
                atomicAdd(&oSum[row0 + 8], s1);
                atomicAdd(&oSumsq[row0 + 8], q1);
            }
        }
    }
}

// ---------------- bottleneck (tensor-core, fp16x3) ----------------
__global__ __launch_bounds__(256)
void bottleneck_tc(const float* __restrict__ W)
{
    const int lane = threadIdx.x & 31;
    const int warp = threadIdx.x >> 5;
    const int o0 = blockIdx.x * 64 + warp * 8;
    const int kb = blockIdx.y * 4096;

    const int r  = lane >> 2;
    const int kq = (lane & 3) * 2;

    const uint32_t* m0 = g_M + (size_t)r * Kbot + kb + kq;
    const uint32_t* m1 = g_M + (size_t)(r + 8) * Kbot + kb + kq;
    const float*    w0 = W + (size_t)(o0 + r) * Kbot + kb + kq;

    float acc[4] = {0.f, 0.f, 0.f, 0.f};

    #pragma unroll 2
    for (int s = 0; s < 4096; s += 16) {
        uint2 u0 = *(const uint2*)(m0 + s);
        uint2 u2 = *(const uint2*)(m0 + s + 8);
        uint2 u1 = *(const uint2*)(m1 + s);
        uint2 u3 = *(const uint2*)(m1 + s + 8);
        float2 wv0 = *(const float2*)(w0 + s);
        float2 wv1 = *(const float2*)(w0 + s + 8);

        uint32_t aH[4], aL[4];
        aH[0] = __byte_perm(u0.x, u0.y, 0x5410);  aL[0] = __byte_perm(u0.x, u0.y, 0x7632);
        aH[1] = __byte_perm(u1.x, u1.y, 0x5410);  aL[1] = __byte_perm(u1.x, u1.y, 0x7632);
        aH[2] = __byte_perm(u2.x, u2.y, 0x5410);  aL[2] = __byte_perm(u2.x, u2.y, 0x7632);
        aH[3] = __byte_perm(u3.x, u3.y, 0x5410);  aL[3] = __byte_perm(u3.x, u3.y, 0x7632);

        uint32_t bH[2], bL[2];
        f16_split2(wv0.x, wv0.y, bH[0], bL[0]);
        f16_split2(wv1.x, wv1.y, bH[1], bL[1]);

        mma_f16_k16(acc, aH, bL);
        mma_f16_k16(acc, aL, bH);
        mma_f16_k16(acc, aH, bH);
    }

    int o = o0 + kq;
    atomicAdd(&g_h[r * Hc + o],           acc[0]);
    atomicAdd(&g_h[r * Hc + o + 1],       acc[1]);
    atomicAdd(&g_h[(r + 8) * Hc + o],     acc[2]);
    atomicAdd(&g_h[(r + 8) * Hc + o + 1], acc[3]);
}

// ---------------- fused bn2d + embedding + L2-norm ----------------
// grid 16 (one block per batch row), 512 threads.
__global__ __launch_bounds__(512)
void emb_fused(const float* __restrict__ bot_b,
               const float* __restrict__ gg, const float* __restrict__ gb,
               const float* __restrict__ Wemb, const float* __restrict__ bemb,
               float* __restrict__ out)
{
    __shared__ float hs[Hc];
    __shared__ float es[Hc];
    __shared__ float red[Hc];

    const int b = blockIdx.x;
    const int o = threadIdx.x;
    const int warp = o >> 5, lane = o & 31;

    // BN over batch (redundant per block; trivial) + relu20 for this row
    {
        float bb = bot_b[o];
        float s = 0.f, q = 0.f, vb = 0.f;
        #pragma unroll
        for (int i = 0; i < Bz; i++) {
            float x = g_h[i * Hc + o] + bb;
            s += x; q += x * x;
            if (i == b) vb = x;
        }
        float m = s * (1.f / 16.f);
        float var = q * (1.f / 16.f) - m * m;
        float a = gg[o] * rsqrtf(var + 1e-5f);
        float d = gb[o] - a * m;
        hs[o] = relu20(a * vb + d);
    }
    __syncthreads();

    // embedding GEMV
    for (int e = warp; e < Hc; e += 16) {
        float s = 0.f;
        for (int c = lane; c < Hc; c += 32)
            s += hs[c] * Wemb[e * Hc + c];
        #pragma unroll
        for (int off = 16; off; off >>= 1)
            s += __shfl_down_sync(0xffffffffu, s, off);
        if (lane == 0) es[e] = s + bemb[e];
    }
    __syncthreads();

    // L2 normalize * 10
    float v = es[o];
    red[o] = v * v;
    __syncthreads();
    for (int st = 256; st > 0; st >>= 1) {
        if (o < st) red[o] += red[o + st];
        __syncthreads();
    }
    float scale = 10.f / sqrtf(red[0] + 1e-10f);
    out[b * Hc + o] = v * scale;
}

// ---------------- launcher ----------------
extern "C" void kernel_launch(void* const* d_in, const int* in_sizes, int n_in,
                              void* d_out, int out_size)
{
    const float* input_x = (const float*)d_in[0];
    const float* conv1_w = (const float*)d_in[1];
    const float* conv1_b = (const float*)d_in[2];
    const float* bn1_g   = (const float*)d_in[3];
    const float* bn1_b   = (const float*)d_in[4];
    const float* conv2_w = (const float*)d_in[5];
    const float* conv2_b = (const float*)d_in[6];
    const float* bn2_g   = (const float*)d_in[7];
    const float* bn2_b   = (const float*)d_in[8];
    const float* conv3_w = (const float*)d_in[9];
    const float* conv3_b = (const float*)d_in[10];
    const float* bn3_g   = (const float*)d_in[11];
    const float* bn3_b   = (const float*)d_in[12];
    const float* lin4_w  = (const float*)d_in[13];
    const float* lin4_b  = (const float*)d_in[14];
    const float* bn4_g   = (const float*)d_in[15];
    const float* bn4_b   = (const float*)d_in[16];
    const float* lin5_w  = (const float*)d_in[17];
    const float* lin5_b  = (const float*)d_in[18];
    const float* bn5_g   = (const float*)d_in[19];
    const float* bn5_b   = (const float*)d_in[20];
    const float* bot_w   = (const float*)d_in[21];
    const float* bot_b   = (const float*)d_in[22];
    const float* bnb_g   = (const float*)d_in[23];
    const float* bnb_b   = (const float*)d_in[24];
    const float* emb_w   = (const float*)d_in[25];
    const float* emb_b   = (const float*)d_in[26];
    float* out = (float*)d_out;

    float *pA, *pZero, *pMf, *pSums, *pSumsqs;
    uint32_t *pAct;
    __half *pWH, *pWL, *pX5H, *pX5L;
    cudaGetSymbolAddress((void**)&pA,     g_bufA);
    cudaGetSymbolAddress((void**)&pAct,   g_act);
    cudaGetSymbolAddress((void**)&pWH,    g_wH);
    cudaGetSymbolAddress((void**)&pWL,    g_wL);
    cudaGetSymbolAddress((void**)&pX5H,   g_x5H);
    cudaGetSymbolAddress((void**)&pX5L,   g_x5L);
    cudaGetSymbolAddress((void**)&pMf,    g_M);
    cudaGetSymbolAddress((void**)&pZero,  g_zero);
    cudaGetSymbolAddress((void**)&pSums,  g_sums);
    cudaGetSymbolAddress((void**)&pSumsqs,g_sumsqs);

    // prep: weight split + transpose/split + zero stats + zero g_h
    prep<<<(WTOT + 255) / 256, 256>>>(input_x, conv1_w, conv2_w, conv3_w,
                                      lin4_w, lin5_w, pAct);

    // conv1: CK=200, T 400->396, N=6336
    conv_gemm_f16k16<5,1,true,false><<<dim3(99, 4, 1), 256>>>(
        pWH + WO1, pWL + WO1, conv1_b, pAct, pA, pSums + 0*Hc, pSumsqs + 0*Hc,
        40, 400, 396, 200, 6336, 0, 0, 0);
    split_bn<false><<<148, 512>>>(pA, pAct, nullptr, nullptr,
                                  pSums + 0*Hc, pSumsqs + 0*Hc, bn1_g, bn1_b,
                                  1.f / 6336.f, 396, Bz * Hc * 396);

    // conv2: CK=1536, T 396->392, N=6272
    conv_gemm_f16k16<3,2,true,false><<<dim3(98, 4, 1), 256>>>(
        pWH + WO2, pWL + WO2, conv2_b, pAct, pA, pSums + 1*Hc, pSumsqs + 1*Hc,
        512, 396, 392, 1536, 6272, 0, 0, 0);
    split_bn<false><<<148, 512>>>(pA, pAct, nullptr, nullptr,
                                  pSums + 1*Hc, pSumsqs + 1*Hc, bn2_g, bn2_b,
                                  1.f / 6272.f, 392, Bz * Hc * 392);

    // conv3: CK=1536, T 392->384, N=6144
    conv_gemm_f16k16<3,4,true,false><<<dim3(96, 4, 1), 256>>>(
        pWH + WO3, pWL + WO3, conv3_b, pAct, pA, pSums + 2*Hc, pSumsqs + 2*Hc,
        512, 392, 384, 1536, 6144, 0, 0, 0);
    split_bn<false><<<148, 512>>>(pA, pAct, nullptr, nullptr,
                                  pSums + 2*Hc, pSumsqs + 2*Hc, bn3_g, bn3_b,
                                  1.f / 6144.f, 384, Bz * Hc * 384);

    // lin4: CK=512, T=384, N=6144
    conv_gemm_f16k16<1,1,true,false><<<dim3(96, 4, 1), 256>>>(
        pWH + WO4, pWL + WO4, lin4_b, pAct, pA, pSums + 3*Hc, pSumsqs + 3*Hc,
        512, 384, 384, 512, 6144, 0, 0, 0);
    split_bn<false><<<148, 512>>>(pA, pAct, nullptr, nullptr,
                                  pSums + 3*Hc, pSumsqs + 3*Hc, bn4_g, bn4_b,
                                  1.f / 6144.f, 384, Bz * Hc * 384);   // x4 split

    // lin5: reads x4 split -> raw x5
    conv_gemm_f16k16<1,1,true,false><<<dim3(96, 4, 1), 256>>>(
        pWH + WO5, pWL + WO5, lin5_b, pAct, pA, pSums + 4*Hc, pSumsqs + 4*Hc,
        512, 384, 384, 512, 6144, 0, 0, 0);
    split_bn<true><<<148, 512>>>(pA, nullptr, pX5H, pX5L,
                                 pSums + 4*Hc, pSumsqs + 4*Hc, bn5_g, bn5_b,
                                 1.f / 6144.f, 384, Bz * Hc * 384);    // x5 planes

    // pooling: writes PACKED split M
    conv_gemm_f16k16<1,1,false,true><<<dim3(8, 4, 16), 256>>>(
        pX5H, pX5L, pZero, pAct, pMf, nullptr, nullptr,
        384, 1, 1, 384, 512, Hc * T3c, Hc * T3c, Kbot);

    // bottleneck: tensor-core fp16x3 (g_h zeroed by prep)
    bottleneck_tc<<<dim3(8, 64), 256>>>(bot_w);

    // fused bn2d + embedding + norm
    emb_fused<<<16, 512>>>(bot_b, bnb_g, bnb_b, emb_w, emb_b, out);
}